// round 2
// baseline (speedup 1.0000x reference)
#include <cuda_runtime.h>

#define NTOK 2048
#define DDIM 768
#define LDIM 16
#define EPSILON_ 0.3f
#define CEXP (1.0f/(4.0f*EPSILON_))

// ---------------- scratch (no allocations allowed) ----------------
__device__ float g_xproj[NTOK*LDIM];
__device__ float g_sqn[NTOK];
__device__ float g_pi[NTOK];
__device__ float g_keps[(size_t)NTOK*NTOK];   // 16.8 MB
__device__ float g_qpart[32*NTOK];            // per-jtile partial rowsums (deterministic)
__device__ float g_v[NTOK];
__device__ float g_d[NTOK];
__device__ float g_target[NTOK*DDIM];
__device__ float g_S[NTOK*DDIM];

// ---------------- kernel A: proj -> LN(16) -> ReLU, + pi head ----------------
__global__ __launch_bounds__(256)
void proj_pi_kernel(const float* __restrict__ x, const float* __restrict__ pw,
                    const float* __restrict__ pb, const float* __restrict__ g1,
                    const float* __restrict__ b1, const float* __restrict__ w1,
                    const float* __restrict__ bb1, const float* __restrict__ w2,
                    const float* __restrict__ bb2)
{
    const int i = blockIdx.x;
    const int t = threadIdx.x;
    __shared__ float xs[DDIM];
    __shared__ float part[256];
    __shared__ float yv[LDIM];
    __shared__ float xp[LDIM];
    __shared__ float stats[2];

    for (int d = t; d < DDIM; d += 256) xs[d] = x[i*DDIM + d];
    __syncthreads();

    // y[l] = x_row . proj_w[:,l]
    const int l = t & 15, g = t >> 4;
    float acc = 0.f;
    for (int d = g; d < DDIM; d += 16) acc += xs[d] * pw[d*LDIM + l];
    part[t] = acc;
    __syncthreads();
    if (t < LDIM) {
        float s = 0.f;
        #pragma unroll
        for (int gg = 0; gg < 16; gg++) s += part[gg*16 + t];
        yv[t] = s + pb[t];
    }
    __syncthreads();
    if (t == 0) {
        float mu = 0.f;
        #pragma unroll
        for (int q = 0; q < LDIM; q++) mu += yv[q];
        mu *= (1.f/LDIM);
        float var = 0.f;
        #pragma unroll
        for (int q = 0; q < LDIM; q++) { float dd = yv[q]-mu; var += dd*dd; }
        var *= (1.f/LDIM);
        stats[0] = mu; stats[1] = rsqrtf(var + 1e-5f);
    }
    __syncthreads();
    if (t < LDIM) {
        float vv = fmaxf((yv[t]-stats[0])*stats[1]*g1[t] + b1[t], 0.f);
        xp[t] = vv;
        g_xproj[i*LDIM + t] = vv;
    }
    __syncthreads();
    if (t == 0) {
        float s = 0.f;
        #pragma unroll
        for (int q = 0; q < LDIM; q++) s += xp[q]*xp[q];
        g_sqn[i] = s;
    }
    float xpr[LDIM];
    #pragma unroll
    for (int q = 0; q < LDIM; q++) xpr[q] = xp[q];

    // pi head: relu(xp @ w1 + bb1) . w2
    float pacc = 0.f;
    for (int dp = t; dp < DDIM; dp += 256) {
        float h = bb1[dp];
        #pragma unroll
        for (int q = 0; q < LDIM; q++) h += xpr[q]*w1[q*DDIM + dp];
        h = fmaxf(h, 0.f);
        pacc += h * w2[dp];
    }
    part[t] = pacc;
    __syncthreads();
    for (int s = 128; s > 0; s >>= 1) {
        if (t < s) part[t] += part[t+s];
        __syncthreads();
    }
    if (t == 0) {
        float z = part[0] + bb2[0];
        g_pi[i] = 1.f/(1.f + __expf(-z));
    }
}

// ---------------- kernel B: K_eps tile (64x64) + partial rowsums ----------------
__global__ __launch_bounds__(256)
void keps_kernel()
{
    const int i0 = blockIdx.y * 64, j0 = blockIdx.x * 64;
    const int t = threadIdx.x;
    const int tx = t & 15, ty = t >> 4;
    __shared__ float xi[64][16];
    __shared__ float xjT[16][64];
    __shared__ float si[64], sj[64];
    __shared__ float rs[64][17];
    {
        const int r = t >> 2, c = (t & 3) * 4;
        float4 a = *(const float4*)&g_xproj[(i0 + r)*LDIM + c];
        *(float4*)&xi[r][c] = a;
        float4 b = *(const float4*)&g_xproj[(j0 + r)*LDIM + c];
        xjT[c+0][r] = b.x; xjT[c+1][r] = b.y; xjT[c+2][r] = b.z; xjT[c+3][r] = b.w;
    }
    if (t < 64) { si[t] = g_sqn[i0+t]; sj[t] = g_sqn[j0+t]; }
    __syncthreads();

    float bj[4][16];
    float sjr[4];
    #pragma unroll
    for (int n = 0; n < 4; n++) {
        const int jj = tx*4 + n;
        sjr[n] = sj[jj];
        #pragma unroll
        for (int q = 0; q < 16; q++) bj[n][q] = xjT[q][jj];
    }
    #pragma unroll
    for (int m = 0; m < 4; m++) {
        const int ii = ty*4 + m;
        float a[16];
        #pragma unroll
        for (int q = 0; q < 16; q++) a[q] = xi[ii][q];
        const float sii = si[ii];
        float o[4]; float rsum = 0.f;
        #pragma unroll
        for (int n = 0; n < 4; n++) {
            float dot = 0.f;
            #pragma unroll
            for (int q = 0; q < 16; q++) dot += a[q]*bj[n][q];
            float kv = __expf(-CEXP*(sii + sjr[n] - 2.f*dot));
            o[n] = kv; rsum += kv;
        }
        *(float4*)&g_keps[(size_t)(i0+ii)*NTOK + j0 + tx*4] =
            make_float4(o[0], o[1], o[2], o[3]);
        rs[ii][tx] = rsum;
    }
    __syncthreads();
    if (t < 64) {
        float s = 0.f;
        #pragma unroll
        for (int c = 0; c < 16; c++) s += rs[t][c];
        g_qpart[blockIdx.x*NTOK + i0 + t] = s;
    }
}

// ---------------- kernel C: v = pi / q_tilde ----------------
__global__ void v_kernel()
{
    const int j = blockIdx.x*256 + threadIdx.x;
    if (j < NTOK) {
        float q = 0.f;
        #pragma unroll
        for (int p = 0; p < 32; p++) q += g_qpart[p*NTOK + j];
        g_v[j] = g_pi[j] / q;
    }
}

// ---------------- SGEMM body: C = A@B (+bias), optionally A cols scaled by v[k] ----
// BM=128, BN=64, BK=8, 256 threads, 8x4 microtile
template<bool SCALE_A, bool ADD_BIAS>
__device__ __forceinline__
void sgemm_body(const float* __restrict__ A, const float* __restrict__ B,
                const float* __restrict__ bias, const float* __restrict__ vscale,
                float* __restrict__ C, int Nn, int K)
{
    __shared__ float As[8][132];   // padded: conflict-free transposed stores
    __shared__ float Bs[8][64];
    const int t  = threadIdx.x;
    const int bm = blockIdx.y * 128, bn = blockIdx.x * 64;
    const int tx = t & 15, ty = t >> 4;

    float acc[8][4] = {};

    const int arow = t >> 1, acol = (t & 1) * 4;     // A: 128x8 as 256 float4
    const int brow = t >> 4, bcol = (t & 15) * 4;    // B: 8x64 as 128 float4 (t<128)
    const float* Aptr = A + (size_t)(bm + arow) * K + acol;
    const float* Bptr = B + (size_t)brow * Nn + bn + bcol;

    for (int k0 = 0; k0 < K; k0 += 8) {
        float4 av = *(const float4*)(Aptr + k0);
        if (SCALE_A) {
            av.x *= vscale[k0+acol+0]; av.y *= vscale[k0+acol+1];
            av.z *= vscale[k0+acol+2]; av.w *= vscale[k0+acol+3];
        }
        As[acol+0][arow] = av.x; As[acol+1][arow] = av.y;
        As[acol+2][arow] = av.z; As[acol+3][arow] = av.w;
        if (t < 128) {
            float4 bv = *(const float4*)(Bptr + (size_t)k0 * Nn);
            *(float4*)&Bs[brow][bcol] = bv;
        }
        __syncthreads();
        #pragma unroll
        for (int k = 0; k < 8; k++) {
            float4 a0 = *(float4*)&As[k][ty*8];
            float4 a1 = *(float4*)&As[k][ty*8+4];
            float4 b0 = *(float4*)&Bs[k][tx*4];
            float avv[8] = {a0.x,a0.y,a0.z,a0.w,a1.x,a1.y,a1.z,a1.w};
            float bvv[4] = {b0.x,b0.y,b0.z,b0.w};
            #pragma unroll
            for (int m = 0; m < 8; m++)
                #pragma unroll
                for (int n = 0; n < 4; n++)
                    acc[m][n] += avv[m]*bvv[n];
        }
        __syncthreads();
    }

    const int crow = bm + ty*8;
    const int ccol = bn + tx*4;
    float4 b4 = make_float4(0.f,0.f,0.f,0.f);
    if (ADD_BIAS) b4 = *(const float4*)&bias[ccol];
    #pragma unroll
    for (int m = 0; m < 8; m++) {
        float4 r = make_float4(acc[m][0]+b4.x, acc[m][1]+b4.y,
                               acc[m][2]+b4.z, acc[m][3]+b4.w);
        *(float4*)&C[(size_t)(crow+m)*Nn + ccol] = r;
    }
}

// target = x @ f_w + f_b   (M=2048, N=768, K=768)
__global__ __launch_bounds__(256)
void gemm_target_kernel(const float* __restrict__ x, const float* __restrict__ fw,
                        const float* __restrict__ fb)
{
    sgemm_body<false,true>(x, fw, fb, nullptr, g_target, DDIM, DDIM);
}

// S = (K_eps * v_col) @ target   (M=2048, N=768, K=2048)
__global__ __launch_bounds__(256)
void gemm_S_kernel()
{
    sgemm_body<true,false>(g_keps, g_target, nullptr, g_v, g_S, DDIM, NTOK);
}

// ---------------- d_i = K_eps[i,:] . v + 1e-5 (one warp per row) ----------------
__global__ __launch_bounds__(256)
void dvec_kernel()
{
    const int w = blockIdx.x * 8 + (threadIdx.x >> 5);
    const int lane = threadIdx.x & 31;
    const float* row = g_keps + (size_t)w * NTOK;
    float s = 0.f;
    for (int j = lane*4; j < NTOK; j += 128) {
        float4 kk = *(const float4*)&row[j];
        float4 vv = *(const float4*)&g_v[j];
        s += kk.x*vv.x + kk.y*vv.y + kk.z*vv.z + kk.w*vv.w;
    }
    #pragma unroll
    for (int off = 16; off; off >>= 1) s += __shfl_down_sync(0xffffffffu, s, off);
    if (lane == 0) g_d[w] = s + 1e-5f;
}

// ---------------- final: combine + LayerNorm(768) ----------------
__global__ __launch_bounds__(256)
void final_kernel(const float* __restrict__ x, const float* __restrict__ dtp,
                  const float* __restrict__ g2, const float* __restrict__ b2,
                  float* __restrict__ out)
{
    const int i = blockIdx.x;
    const int t = threadIdx.x;
    const float dtv = dtp[0];
    const float invd = (1.f/EPSILON_) / g_d[i];

    float vals[3];
    float sum = 0.f, sq = 0.f;
    #pragma unroll
    for (int c = 0; c < 3; c++) {
        const int d = t + c*256;
        const float tg = g_target[(size_t)i*DDIM + d];
        const float tt = dtv * (invd * g_S[(size_t)i*DDIM + d] - tg);
        const float t2 = 0.7f * x[(size_t)i*DDIM + d] + 0.3f*(tg + 2.f*tt);
        vals[c] = t2; sum += t2; sq += t2*t2;
    }
    __shared__ float rsm[256], rqm[256];
    __shared__ float mu_s, is_s;
    rsm[t] = sum; rqm[t] = sq;
    __syncthreads();
    for (int s = 128; s > 0; s >>= 1) {
        if (t < s) { rsm[t] += rsm[t+s]; rqm[t] += rqm[t+s]; }
        __syncthreads();
    }
    if (t == 0) {
        float mu = rsm[0] * (1.f/DDIM);
        float var = rqm[0] * (1.f/DDIM) - mu*mu;
        mu_s = mu; is_s = rsqrtf(var + 1e-5f);
    }
    __syncthreads();
    #pragma unroll
    for (int c = 0; c < 3; c++) {
        const int d = t + c*256;
        out[(size_t)i*DDIM + d] = (vals[c]-mu_s)*is_s*g2[d] + b2[d];
    }
}

// ---------------- launch (pure kernel launches; nothing else) ----------------
extern "C" void kernel_launch(void* const* d_in, const int* in_sizes, int n_in,
                              void* d_out, int out_size)
{
    const float* x      = (const float*)d_in[0];
    const float* proj_w = (const float*)d_in[1];
    const float* proj_b = (const float*)d_in[2];
    const float* ln1_g  = (const float*)d_in[3];
    const float* ln1_b  = (const float*)d_in[4];
    const float* pi_w1  = (const float*)d_in[5];
    const float* pi_b1  = (const float*)d_in[6];
    const float* pi_w2  = (const float*)d_in[7];
    const float* pi_b2  = (const float*)d_in[8];
    const float* dt     = (const float*)d_in[9];
    const float* f_w    = (const float*)d_in[10];
    const float* f_b    = (const float*)d_in[11];
    const float* ln2_g  = (const float*)d_in[12];
    const float* ln2_b  = (const float*)d_in[13];
    float* out = (float*)d_out;

    proj_pi_kernel<<<NTOK, 256>>>(x, proj_w, proj_b, ln1_g, ln1_b,
                                  pi_w1, pi_b1, pi_w2, pi_b2);
    keps_kernel<<<dim3(32,32), 256>>>();
    v_kernel<<<8, 256>>>();
    gemm_target_kernel<<<dim3(DDIM/64, NTOK/128), 256>>>(x, f_w, f_b);
    dvec_kernel<<<NTOK/8, 256>>>();
    gemm_S_kernel<<<dim3(DDIM/64, NTOK/128), 256>>>();
    final_kernel<<<NTOK, 256>>>(x, dt, ln2_g, ln2_b, out);
}

// round 4
// speedup vs baseline: 2.5892x; 2.5892x over previous
#include <cuda_runtime.h>
#include <cuda_bf16.h>
#include <cstdint>

#define NTOK 2048
#define DDIM 768
#define LDIM 16
#define EPSILON_ 0.3f
#define CEXP (1.0f/(4.0f*EPSILON_))

// ---------------- scratch (no allocations allowed) ----------------
__device__ float g_xproj[NTOK*LDIM];
__device__ float g_sqn[NTOK];
__device__ float g_pi[NTOK];
__device__ __nv_bfloat16 g_khi[(size_t)NTOK*NTOK];   // 8.4 MB
__device__ __nv_bfloat16 g_klo[(size_t)NTOK*NTOK];   // 8.4 MB
__device__ float g_qpart[32*NTOK];
__device__ float g_v[NTOK];
__device__ float g_d[NTOK];
__device__ float g_target[NTOK*DDIM];
__device__ float g_S[NTOK*DDIM];
__device__ __nv_bfloat16 g_xhi[NTOK*DDIM];
__device__ __nv_bfloat16 g_xlo[NTOK*DDIM];
__device__ __nv_bfloat16 g_fwThi[DDIM*DDIM];  // f_w^T : [n, k]
__device__ __nv_bfloat16 g_fwTlo[DDIM*DDIM];
__device__ __nv_bfloat16 g_tvthi[DDIM*NTOK];  // (v*target)^T : [n, k]
__device__ __nv_bfloat16 g_tvtlo[DDIM*NTOK];

// ---------------- warp-MMA helpers (baseline PTX, compute_103-safe) ----------
__device__ __forceinline__ uint32_t smem_u32(const void* p) {
    uint32_t a;
    asm("{ .reg .u64 t; cvta.to.shared.u64 t, %1; cvt.u32.u64 %0, t; }" : "=r"(a) : "l"(p));
    return a;
}
__device__ __forceinline__ void ldsm_x4(uint32_t* r, uint32_t addr) {
    asm volatile("ldmatrix.sync.aligned.m8n8.x4.shared.b16 {%0,%1,%2,%3}, [%4];"
        : "=r"(r[0]), "=r"(r[1]), "=r"(r[2]), "=r"(r[3]) : "r"(addr));
}
__device__ __forceinline__ void mma16816(float* c, const uint32_t* a, const uint32_t* b) {
    asm volatile("mma.sync.aligned.m16n8k16.row.col.f32.bf16.bf16.f32 "
        "{%0,%1,%2,%3}, {%4,%5,%6,%7}, {%8,%9}, {%0,%1,%2,%3};"
        : "+f"(c[0]), "+f"(c[1]), "+f"(c[2]), "+f"(c[3])
        : "r"(a[0]), "r"(a[1]), "r"(a[2]), "r"(a[3]), "r"(b[0]), "r"(b[1]));
}

// ---------------- kernel A: proj -> LN(16) -> ReLU, + pi head ----------------
__global__ __launch_bounds__(256)
void proj_pi_kernel(const float* __restrict__ x, const float* __restrict__ pw,
                    const float* __restrict__ pb, const float* __restrict__ g1,
                    const float* __restrict__ b1, const float* __restrict__ w1,
                    const float* __restrict__ bb1, const float* __restrict__ w2,
                    const float* __restrict__ bb2)
{
    const int i = blockIdx.x;
    const int t = threadIdx.x;
    __shared__ float xs[DDIM];
    __shared__ float part[256];
    __shared__ float yv[LDIM];
    __shared__ float xp[LDIM];
    __shared__ float stats[2];

    for (int d = t; d < DDIM; d += 256) xs[d] = x[i*DDIM + d];
    __syncthreads();

    const int l = t & 15, g = t >> 4;
    float acc = 0.f;
    for (int d = g; d < DDIM; d += 16) acc += xs[d] * pw[d*LDIM + l];
    part[t] = acc;
    __syncthreads();
    if (t < LDIM) {
        float s = 0.f;
        #pragma unroll
        for (int gg = 0; gg < 16; gg++) s += part[gg*16 + t];
        yv[t] = s + pb[t];
    }
    __syncthreads();
    if (t == 0) {
        float mu = 0.f;
        #pragma unroll
        for (int q = 0; q < LDIM; q++) mu += yv[q];
        mu *= (1.f/LDIM);
        float var = 0.f;
        #pragma unroll
        for (int q = 0; q < LDIM; q++) { float dd = yv[q]-mu; var += dd*dd; }
        var *= (1.f/LDIM);
        stats[0] = mu; stats[1] = rsqrtf(var + 1e-5f);
    }
    __syncthreads();
    if (t < LDIM) {
        float vv = fmaxf((yv[t]-stats[0])*stats[1]*g1[t] + b1[t], 0.f);
        xp[t] = vv;
        g_xproj[i*LDIM + t] = vv;
    }
    __syncthreads();
    if (t == 0) {
        float s = 0.f;
        #pragma unroll
        for (int q = 0; q < LDIM; q++) s += xp[q]*xp[q];
        g_sqn[i] = s;
    }
    float xpr[LDIM];
    #pragma unroll
    for (int q = 0; q < LDIM; q++) xpr[q] = xp[q];

    float pacc = 0.f;
    for (int dp = t; dp < DDIM; dp += 256) {
        float h = bb1[dp];
        #pragma unroll
        for (int q = 0; q < LDIM; q++) h += xpr[q]*w1[q*DDIM + dp];
        h = fmaxf(h, 0.f);
        pacc += h * w2[dp];
    }
    part[t] = pacc;
    __syncthreads();
    for (int s = 128; s > 0; s >>= 1) {
        if (t < s) part[t] += part[t+s];
        __syncthreads();
    }
    if (t == 0) {
        float z = part[0] + bb2[0];
        g_pi[i] = 1.f/(1.f + __expf(-z));
    }
}

// ---------------- kernel B: K_eps tile (64x64) -> bf16 hi/lo + partial rowsums ----
__global__ __launch_bounds__(256)
void keps_kernel()
{
    const int i0 = blockIdx.y * 64, j0 = blockIdx.x * 64;
    const int t = threadIdx.x;
    const int tx = t & 15, ty = t >> 4;
    __shared__ float xi[64][16];
    __shared__ float xjT[16][64];
    __shared__ float si[64], sj[64];
    __shared__ float rs[64][17];
    {
        const int r = t >> 2, c = (t & 3) * 4;
        float4 a = *(const float4*)&g_xproj[(i0 + r)*LDIM + c];
        *(float4*)&xi[r][c] = a;
        float4 b = *(const float4*)&g_xproj[(j0 + r)*LDIM + c];
        xjT[c+0][r] = b.x; xjT[c+1][r] = b.y; xjT[c+2][r] = b.z; xjT[c+3][r] = b.w;
    }
    if (t < 64) { si[t] = g_sqn[i0+t]; sj[t] = g_sqn[j0+t]; }
    __syncthreads();

    float bj[4][16];
    float sjr[4];
    #pragma unroll
    for (int n = 0; n < 4; n++) {
        const int jj = tx*4 + n;
        sjr[n] = sj[jj];
        #pragma unroll
        for (int q = 0; q < 16; q++) bj[n][q] = xjT[q][jj];
    }
    #pragma unroll
    for (int m = 0; m < 4; m++) {
        const int ii = ty*4 + m;
        float a[16];
        #pragma unroll
        for (int q = 0; q < 16; q++) a[q] = xi[ii][q];
        const float sii = si[ii];
        float o[4]; float rsum = 0.f;
        #pragma unroll
        for (int n = 0; n < 4; n++) {
            float dot = 0.f;
            #pragma unroll
            for (int q = 0; q < 16; q++) dot += a[q]*bj[n][q];
            float kv = __expf(-CEXP*(sii + sjr[n] - 2.f*dot));
            o[n] = kv; rsum += kv;
        }
        const size_t base = (size_t)(i0+ii)*NTOK + j0 + tx*4;
        float h0 = __bfloat162float(__float2bfloat16(o[0]));
        float h1 = __bfloat162float(__float2bfloat16(o[1]));
        float h2 = __bfloat162float(__float2bfloat16(o[2]));
        float h3 = __bfloat162float(__float2bfloat16(o[3]));
        *(__nv_bfloat162*)&g_khi[base]   = __floats2bfloat162_rn(h0, h1);
        *(__nv_bfloat162*)&g_khi[base+2] = __floats2bfloat162_rn(h2, h3);
        *(__nv_bfloat162*)&g_klo[base]   = __floats2bfloat162_rn(o[0]-h0, o[1]-h1);
        *(__nv_bfloat162*)&g_klo[base+2] = __floats2bfloat162_rn(o[2]-h2, o[3]-h3);
        rs[ii][tx] = rsum;
    }
    __syncthreads();
    if (t < 64) {
        float s = 0.f;
        #pragma unroll
        for (int c = 0; c < 16; c++) s += rs[t][c];
        g_qpart[blockIdx.x*NTOK + i0 + t] = s;
    }
}

// ---------------- kernel C: v = pi / q_tilde ----------------
__global__ void v_kernel()
{
    const int j = blockIdx.x*256 + threadIdx.x;
    if (j < NTOK) {
        float q = 0.f;
        #pragma unroll
        for (int p = 0; p < 32; p++) q += g_qpart[p*NTOK + j];
        g_v[j] = g_pi[j] / q;
    }
}

// ---------------- split x -> bf16 hi/lo (elementwise) ----------------
__global__ __launch_bounds__(256)
void split_x_kernel(const float* __restrict__ src)
{
    const int i = blockIdx.x*256 + threadIdx.x;
    const float f = src[i];
    const float h = __bfloat162float(__float2bfloat16(f));
    g_xhi[i] = __float2bfloat16(h);
    g_xlo[i] = __float2bfloat16(f - h);
}

// ---------------- transpose + (optional row scale) + split -------------
template<bool SCALE>
__device__ __forceinline__
void transpose_split_body(const float* __restrict__ in, const float* __restrict__ scale,
                          __nv_bfloat16* __restrict__ hi, __nv_bfloat16* __restrict__ lo,
                          int R, int Ccols)
{
    __shared__ float tile[32][33];
    const int r0 = blockIdx.y*32, c0 = blockIdx.x*32;
    const int tx = threadIdx.x & 31, ty0 = threadIdx.x >> 5;
    #pragma unroll
    for (int p = 0; p < 4; p++) {
        const int ty = ty0 + p*8;
        float vv = in[(size_t)(r0+ty)*Ccols + c0+tx];
        if (SCALE) vv *= scale[r0+ty];
        tile[ty][tx] = vv;
    }
    __syncthreads();
    #pragma unroll
    for (int p = 0; p < 4; p++) {
        const int ty = ty0 + p*8;
        const float f = tile[tx][ty];
        const float h = __bfloat162float(__float2bfloat16(f));
        const size_t o = (size_t)(c0+ty)*R + r0+tx;
        hi[o] = __float2bfloat16(h);
        lo[o] = __float2bfloat16(f - h);
    }
}

__global__ __launch_bounds__(256)
void transpose_fw_kernel(const float* __restrict__ fw)
{
    transpose_split_body<false>(fw, nullptr, g_fwThi, g_fwTlo, DDIM, DDIM);
}
__global__ __launch_bounds__(256)
void transpose_tvt_kernel()
{
    transpose_split_body<true>(g_target, g_v, g_tvthi, g_tvtlo, NTOK, DDIM);
}

// ---------------- warp-MMA GEMM: C[M,768] = (Ahi+Alo)@(Bhi+Blo)^T (+bias) ------
// A: [2048, K] bf16 K-major. B: [768, K] bf16 K-major. C f32 row-major (stride 768).
// BM=128 BN=64 BK=32, 8 warps (4 M x 2 N), warp tile 32x32, m16n8k16 frags.
#define APAD 40   // padded row length (bf16 elems): conflict-free ldmatrix
template<bool ADD_BIAS>
__device__ __forceinline__
void gemm_mma_body(const __nv_bfloat16* __restrict__ Ahi, const __nv_bfloat16* __restrict__ Alo,
                   const __nv_bfloat16* __restrict__ Bhi, const __nv_bfloat16* __restrict__ Blo,
                   const float* __restrict__ bias, float* __restrict__ C, int K)
{
    __shared__ __align__(16) __nv_bfloat16 sA[2][128*APAD];  // [hi/lo]
    __shared__ __align__(16) __nv_bfloat16 sB[2][64*APAD];
    const int tid = threadIdx.x;
    const int lane = tid & 31, w = tid >> 5;
    const int wm = w & 3, wn = w >> 2;
    const int m0 = blockIdx.y * 128, n0 = blockIdx.x * 64;

    // ldmatrix per-lane base addresses (byte offsets into smem)
    const uint32_t sA0 = smem_u32(sA[0]), sA1 = smem_u32(sA[1]);
    const uint32_t sB0 = smem_u32(sB[0]), sB1 = smem_u32(sB[1]);
    const uint32_t aRow = wm*32 + (lane & 7) + ((lane >> 3) & 1)*8;
    const uint32_t aCol = ((lane >> 4) & 1)*8;
    const uint32_t bRow = wn*32 + ((lane >> 4) & 1)*8 + (lane & 7);
    const uint32_t bCol = ((lane >> 3) & 1)*8;
    uint32_t aAddr[2][2], bAddr[2][2];   // [mt][mat], [np][mat]
    #pragma unroll
    for (int mt = 0; mt < 2; mt++) {
        const uint32_t off = ((aRow + mt*16)*APAD + aCol)*2;
        aAddr[mt][0] = sA0 + off; aAddr[mt][1] = sA1 + off;
    }
    #pragma unroll
    for (int np = 0; np < 2; np++) {
        const uint32_t off = ((bRow + np*16)*APAD + bCol)*2;
        bAddr[np][0] = sB0 + off; bAddr[np][1] = sB1 + off;
    }

    float acc[2][4][4] = {};

    for (int kof = 0; kof < K; kof += 32) {
        // load 1536 uint4: Ahi(512) Alo(512) Bhi(256) Blo(256)
        #pragma unroll
        for (int it = 0; it < 6; it++) {
            const int idx = tid + it*256;
            if (idx < 1024) {
                const int mat = idx >> 9, r = (idx >> 2) & 127, q = idx & 3;
                const __nv_bfloat16* src = (mat ? Alo : Ahi) + (size_t)(m0+r)*K + kof + q*8;
                *(uint4*)&sA[mat][r*APAD + q*8] = *(const uint4*)src;
            } else {
                const int j = idx - 1024;
                const int mat = j >> 8, r = (j >> 2) & 63, q = j & 3;
                const __nv_bfloat16* src = (mat ? Blo : Bhi) + (size_t)(n0+r)*K + kof + q*8;
                *(uint4*)&sB[mat][r*APAD + q*8] = *(const uint4*)src;
            }
        }
        __syncthreads();

        #pragma unroll
        for (int kk = 0; kk < 2; kk++) {
            const uint32_t kb = kk * 32;  // 16 elems * 2 bytes
            uint32_t Af[2][2][4], Bf[2][2][4];
            #pragma unroll
            for (int mt = 0; mt < 2; mt++) {
                ldsm_x4(Af[mt][0], aAddr[mt][0] + kb);
                ldsm_x4(Af[mt][1], aAddr[mt][1] + kb);
            }
            #pragma unroll
            for (int np = 0; np < 2; np++) {
                ldsm_x4(Bf[np][0], bAddr[np][0] + kb);
                ldsm_x4(Bf[np][1], bAddr[np][1] + kb);
            }
            #pragma unroll
            for (int mt = 0; mt < 2; mt++) {
                #pragma unroll
                for (int j = 0; j < 4; j++) {
                    float* c = acc[mt][j];
                    const int np = j >> 1, o = (j & 1)*2;
                    mma16816(c, Af[mt][0], &Bf[np][0][o]);   // hi*hi
                    mma16816(c, Af[mt][0], &Bf[np][1][o]);   // hi*lo
                    mma16816(c, Af[mt][1], &Bf[np][0][o]);   // lo*hi
                }
            }
        }
        __syncthreads();
    }

    // epilogue: c0,c1 -> (row g, col 2tg..+1); c2,c3 -> (row g+8)
    const int g = lane >> 2, tg2 = (lane & 3)*2;
    #pragma unroll
    for (int mt = 0; mt < 2; mt++) {
        const int row = m0 + wm*32 + mt*16 + g;
        #pragma unroll
        for (int j = 0; j < 4; j++) {
            const int col = n0 + wn*32 + j*8 + tg2;
            float b0 = 0.f, b1 = 0.f;
            if (ADD_BIAS) { b0 = bias[col]; b1 = bias[col+1]; }
            *(float2*)&C[(size_t)row*DDIM + col] =
                make_float2(acc[mt][j][0] + b0, acc[mt][j][1] + b1);
            *(float2*)&C[(size_t)(row+8)*DDIM + col] =
                make_float2(acc[mt][j][2] + b0, acc[mt][j][3] + b1);
        }
    }
}

// target = x @ f_w + f_b   (K=768)
__global__ __launch_bounds__(256)
void gemm_target_kernel(const float* __restrict__ fb)
{
    gemm_mma_body<true>(g_xhi, g_xlo, g_fwThi, g_fwTlo, fb, g_target, DDIM);
}
// S = K_eps @ (v*target)   (K=2048)
__global__ __launch_bounds__(256)
void gemm_S_kernel()
{
    gemm_mma_body<false>(g_khi, g_klo, g_tvthi, g_tvtlo, nullptr, g_S, NTOK);
}

// ---------------- d_i = K_eps[i,:] . v + 1e-5 (one warp per row, bf16 K) ----------
__global__ __launch_bounds__(256)
void dvec_kernel()
{
    const int w = blockIdx.x * 8 + (threadIdx.x >> 5);
    const int lane = threadIdx.x & 31;
    const size_t base = (size_t)w * NTOK;
    float s = 0.f;
    for (int j = lane*2; j < NTOK; j += 64) {
        __nv_bfloat162 h2 = *(const __nv_bfloat162*)&g_khi[base + j];
        __nv_bfloat162 l2 = *(const __nv_bfloat162*)&g_klo[base + j];
        float2 vv = *(const float2*)&g_v[j];
        s += (__bfloat162float(h2.x) + __bfloat162float(l2.x)) * vv.x
           + (__bfloat162float(h2.y) + __bfloat162float(l2.y)) * vv.y;
    }
    #pragma unroll
    for (int off = 16; off; off >>= 1) s += __shfl_down_sync(0xffffffffu, s, off);
    if (lane == 0) g_d[w] = s + 1e-5f;
}

// ---------------- final: combine + LayerNorm(768) ----------------
__global__ __launch_bounds__(256)
void final_kernel(const float* __restrict__ x, const float* __restrict__ dtp,
                  const float* __restrict__ g2, const float* __restrict__ b2,
                  float* __restrict__ out)
{
    const int i = blockIdx.x;
    const int t = threadIdx.x;
    const float dtv = dtp[0];
    const float invd = (1.f/EPSILON_) / g_d[i];

    float vals[3];
    float sum = 0.f, sq = 0.f;
    #pragma unroll
    for (int c = 0; c < 3; c++) {
        const int d = t + c*256;
        const float tg = g_target[(size_t)i*DDIM + d];
        const float tt = dtv * (invd * g_S[(size_t)i*DDIM + d] - tg);
        const float t2 = 0.7f * x[(size_t)i*DDIM + d] + 0.3f*(tg + 2.f*tt);
        vals[c] = t2; sum += t2; sq += t2*t2;
    }
    __shared__ float rsm[256], rqm[256];
    __shared__ float mu_s, is_s;
    rsm[t] = sum; rqm[t] = sq;
    __syncthreads();
    for (int s = 128; s > 0; s >>= 1) {
        if (t < s) { rsm[t] += rsm[t+s]; rqm[t] += rqm[t+s]; }
        __syncthreads();
    }
    if (t == 0) {
        float mu = rsm[0] * (1.f/DDIM);
        float var = rqm[0] * (1.f/DDIM) - mu*mu;
        mu_s = mu; is_s = rsqrtf(var + 1e-5f);
    }
    __syncthreads();
    #pragma unroll
    for (int c = 0; c < 3; c++) {
        const int d = t + c*256;
        out[(size_t)i*DDIM + d] = (vals[c]-mu_s)*is_s*g2[d] + b2[d];
    }
}

// ---------------- launch (pure kernel launches; nothing else) ----------------
extern "C" void kernel_launch(void* const* d_in, const int* in_sizes, int n_in,
                              void* d_out, int out_size)
{
    const float* x      = (const float*)d_in[0];
    const float* proj_w = (const float*)d_in[1];
    const float* proj_b = (const float*)d_in[2];
    const float* ln1_g  = (const float*)d_in[3];
    const float* ln1_b  = (const float*)d_in[4];
    const float* pi_w1  = (const float*)d_in[5];
    const float* pi_b1  = (const float*)d_in[6];
    const float* pi_w2  = (const float*)d_in[7];
    const float* pi_b2  = (const float*)d_in[8];
    const float* dt     = (const float*)d_in[9];
    const float* f_w    = (const float*)d_in[10];
    const float* f_b    = (const float*)d_in[11];
    const float* ln2_g  = (const float*)d_in[12];
    const float* ln2_b  = (const float*)d_in[13];
    float* out = (float*)d_out;

    proj_pi_kernel<<<NTOK, 256>>>(x, proj_w, proj_b, ln1_g, ln1_b,
                                  pi_w1, pi_b1, pi_w2, pi_b2);
    split_x_kernel<<<(NTOK*DDIM)/256, 256>>>(x);
    transpose_fw_kernel<<<dim3(DDIM/32, DDIM/32), 256>>>(f_w);
    keps_kernel<<<dim3(32,32), 256>>>();
    v_kernel<<<8, 256>>>();
    gemm_target_kernel<<<dim3(DDIM/64, NTOK/128), 256>>>(f_b);
    transpose_tvt_kernel<<<dim3(DDIM/32, NTOK/32), 256>>>();
    dvec_kernel<<<NTOK/8, 256>>>();
    gemm_S_kernel<<<dim3(DDIM/64, NTOK/128), 256>>>();
    final_kernel<<<NTOK, 256>>>(x, dt, ln2_g, ln2_b, out);
}

// round 5
// speedup vs baseline: 3.7128x; 1.4340x over previous
#include <cuda_runtime.h>
#include <cuda_bf16.h>
#include <cstdint>

#define NTOK 2048
#define DDIM 768
#define LDIM 16
#define EPSILON_ 0.3f
#define CEXP (1.0f/(4.0f*EPSILON_))

// ---------------- scratch (no allocations allowed) ----------------
__device__ float g_xproj[NTOK*LDIM];
__device__ float g_sqn[NTOK];
__device__ float g_pi[NTOK];
__device__ __nv_bfloat16 g_khi[(size_t)NTOK*NTOK];   // 8.4 MB
__device__ __nv_bfloat16 g_klo[(size_t)NTOK*NTOK];   // 8.4 MB
__device__ float g_qpart[32*NTOK];
__device__ float g_v[NTOK];
__device__ float g_d[NTOK];
__device__ float g_target[NTOK*DDIM];
__device__ float g_S[NTOK*DDIM];
__device__ __nv_bfloat16 g_xhi[NTOK*DDIM];
__device__ __nv_bfloat16 g_xlo[NTOK*DDIM];
__device__ __nv_bfloat16 g_fwThi[DDIM*DDIM];  // f_w^T : [n, k]
__device__ __nv_bfloat16 g_fwTlo[DDIM*DDIM];
__device__ __nv_bfloat16 g_tvthi[DDIM*NTOK];  // (v*target)^T : [n, k]
__device__ __nv_bfloat16 g_tvtlo[DDIM*NTOK];

// ---------------- warp-MMA / cp.async helpers (baseline PTX) ----------
__device__ __forceinline__ uint32_t smem_u32(const void* p) {
    uint32_t a;
    asm("{ .reg .u64 t; cvta.to.shared.u64 t, %1; cvt.u32.u64 %0, t; }" : "=r"(a) : "l"(p));
    return a;
}
__device__ __forceinline__ void ldsm_x4(uint32_t* r, uint32_t addr) {
    asm volatile("ldmatrix.sync.aligned.m8n8.x4.shared.b16 {%0,%1,%2,%3}, [%4];"
        : "=r"(r[0]), "=r"(r[1]), "=r"(r[2]), "=r"(r[3]) : "r"(addr));
}
__device__ __forceinline__ void mma16816(float* c, const uint32_t* a, const uint32_t* b) {
    asm volatile("mma.sync.aligned.m16n8k16.row.col.f32.bf16.bf16.f32 "
        "{%0,%1,%2,%3}, {%4,%5,%6,%7}, {%8,%9}, {%0,%1,%2,%3};"
        : "+f"(c[0]), "+f"(c[1]), "+f"(c[2]), "+f"(c[3])
        : "r"(a[0]), "r"(a[1]), "r"(a[2]), "r"(a[3]), "r"(b[0]), "r"(b[1]));
}
__device__ __forceinline__ void cp16(uint32_t dst, uint64_t gsrc) {
    asm volatile("cp.async.ca.shared.global [%0], [%1], 16;" :: "r"(dst), "l"(gsrc) : "memory");
}
#define CP_COMMIT() asm volatile("cp.async.commit_group;" ::: "memory")
#define CP_WAIT1()  asm volatile("cp.async.wait_group 1;" ::: "memory")
#define CP_WAIT0()  asm volatile("cp.async.wait_group 0;" ::: "memory")

// ---------------- kernel A: proj -> LN(16) -> ReLU, + pi head (4 rows/block) ----
__global__ __launch_bounds__(256)
void proj_pi_kernel(const float* __restrict__ x, const float* __restrict__ pw,
                    const float* __restrict__ pb, const float* __restrict__ g1,
                    const float* __restrict__ b1, const float* __restrict__ w1,
                    const float* __restrict__ bb1, const float* __restrict__ w2,
                    const float* __restrict__ bb2)
{
    const int i0 = blockIdx.x * 4;
    const int t = threadIdx.x;
    const int lane = t & 31, wid = t >> 5;
    __shared__ float xs[4][DDIM];
    __shared__ float part[256];
    __shared__ float yv[4][LDIM];
    __shared__ float xp[4][LDIM];
    __shared__ float red[4][8];

    #pragma unroll
    for (int r = 0; r < 4; r++)
        for (int d = t; d < DDIM; d += 256) xs[r][d] = x[(size_t)(i0+r)*DDIM + d];
    __syncthreads();

    // proj: y[r][l] = x_row[r] . proj_w[:,l]
    const int l = t & 15, g = t >> 4;
    float accs[4] = {};
    for (int d = g; d < DDIM; d += 16) {
        const float w = pw[d*LDIM + l];
        accs[0] += xs[0][d]*w; accs[1] += xs[1][d]*w;
        accs[2] += xs[2][d]*w; accs[3] += xs[3][d]*w;
    }
    #pragma unroll
    for (int r = 0; r < 4; r++) {
        __syncthreads();
        part[t] = accs[r];
        __syncthreads();
        if (t < LDIM) {
            float s = 0.f;
            #pragma unroll
            for (int gg = 0; gg < 16; gg++) s += part[gg*16 + t];
            yv[r][t] = s + pb[t];
        }
    }
    __syncthreads();
    // LN(16) + ReLU per row: threads 0..3
    if (t < 4) {
        float mu = 0.f;
        #pragma unroll
        for (int q = 0; q < LDIM; q++) mu += yv[t][q];
        mu *= (1.f/LDIM);
        float var = 0.f;
        #pragma unroll
        for (int q = 0; q < LDIM; q++) { float dd = yv[t][q]-mu; var += dd*dd; }
        var *= (1.f/LDIM);
        const float is = rsqrtf(var + 1e-5f);
        float sq = 0.f;
        #pragma unroll
        for (int q = 0; q < LDIM; q++) {
            float vv = fmaxf((yv[t][q]-mu)*is*g1[q] + b1[q], 0.f);
            xp[t][q] = vv; sq += vv*vv;
        }
        g_sqn[i0+t] = sq;
    }
    __syncthreads();
    if (t < 64) g_xproj[(i0 + (t>>4))*LDIM + (t&15)] = xp[t>>4][t&15];

    // pi head: sigmoid(relu(xp @ w1 + b1) . w2 + b2), weight cols read once for 4 rows
    float pacc[4] = {};
    for (int dp = t; dp < DDIM; dp += 256) {
        const float bb = bb1[dp], wo = w2[dp];
        float wc[16];
        #pragma unroll
        for (int q = 0; q < 16; q++) wc[q] = w1[q*DDIM + dp];
        #pragma unroll
        for (int r = 0; r < 4; r++) {
            float h = bb;
            #pragma unroll
            for (int q = 0; q < 16; q++) h += xp[r][q]*wc[q];
            h = fmaxf(h, 0.f);
            pacc[r] += h * wo;
        }
    }
    #pragma unroll
    for (int r = 0; r < 4; r++) {
        float v = pacc[r];
        #pragma unroll
        for (int off = 16; off; off >>= 1) v += __shfl_down_sync(0xffffffffu, v, off);
        if (lane == 0) red[r][wid] = v;
    }
    __syncthreads();
    if (t < 4) {
        float s = 0.f;
        #pragma unroll
        for (int q = 0; q < 8; q++) s += red[t][q];
        g_pi[i0+t] = 1.f/(1.f + __expf(-(s + bb2[0])));
    }
}

// ---------------- kernel B: K_eps tile (64x64) -> bf16 hi/lo + partial rowsums ----
__global__ __launch_bounds__(256)
void keps_kernel()
{
    const int i0 = blockIdx.y * 64, j0 = blockIdx.x * 64;
    const int t = threadIdx.x;
    const int tx = t & 15, ty = t >> 4;
    __shared__ float xi[64][16];
    __shared__ float xjT[16][64];
    __shared__ float si[64], sj[64];
    __shared__ float rs[64][17];
    {
        const int r = t >> 2, c = (t & 3) * 4;
        float4 a = *(const float4*)&g_xproj[(i0 + r)*LDIM + c];
        *(float4*)&xi[r][c] = a;
        float4 b = *(const float4*)&g_xproj[(j0 + r)*LDIM + c];
        xjT[c+0][r] = b.x; xjT[c+1][r] = b.y; xjT[c+2][r] = b.z; xjT[c+3][r] = b.w;
    }
    if (t < 64) { si[t] = g_sqn[i0+t]; sj[t] = g_sqn[j0+t]; }
    __syncthreads();

    float bj[4][16];
    float sjr[4];
    #pragma unroll
    for (int n = 0; n < 4; n++) {
        const int jj = tx*4 + n;
        sjr[n] = sj[jj];
        #pragma unroll
        for (int q = 0; q < 16; q++) bj[n][q] = xjT[q][jj];
    }
    #pragma unroll
    for (int m = 0; m < 4; m++) {
        const int ii = ty*4 + m;
        float a[16];
        #pragma unroll
        for (int q = 0; q < 16; q++) a[q] = xi[ii][q];
        const float sii = si[ii];
        float o[4]; float rsum = 0.f;
        #pragma unroll
        for (int n = 0; n < 4; n++) {
            float dot = 0.f;
            #pragma unroll
            for (int q = 0; q < 16; q++) dot += a[q]*bj[n][q];
            float kv = __expf(-CEXP*(sii + sjr[n] - 2.f*dot));
            o[n] = kv; rsum += kv;
        }
        const size_t base = (size_t)(i0+ii)*NTOK + j0 + tx*4;
        float h0 = __bfloat162float(__float2bfloat16(o[0]));
        float h1 = __bfloat162float(__float2bfloat16(o[1]));
        float h2 = __bfloat162float(__float2bfloat16(o[2]));
        float h3 = __bfloat162float(__float2bfloat16(o[3]));
        *(__nv_bfloat162*)&g_khi[base]   = __floats2bfloat162_rn(h0, h1);
        *(__nv_bfloat162*)&g_khi[base+2] = __floats2bfloat162_rn(h2, h3);
        *(__nv_bfloat162*)&g_klo[base]   = __floats2bfloat162_rn(o[0]-h0, o[1]-h1);
        *(__nv_bfloat162*)&g_klo[base+2] = __floats2bfloat162_rn(o[2]-h2, o[3]-h3);
        rs[ii][tx] = rsum;
    }
    __syncthreads();
    if (t < 64) {
        float s = 0.f;
        #pragma unroll
        for (int c = 0; c < 16; c++) s += rs[t][c];
        g_qpart[blockIdx.x*NTOK + i0 + t] = s;
    }
}

// ---------------- kernel C: v = pi / q_tilde ----------------
__global__ void v_kernel()
{
    const int j = blockIdx.x*256 + threadIdx.x;
    if (j < NTOK) {
        float q = 0.f;
        #pragma unroll
        for (int p = 0; p < 32; p++) q += g_qpart[p*NTOK + j];
        g_v[j] = g_pi[j] / q;
    }
}

// ---------------- split x -> bf16 hi/lo (elementwise) ----------------
__global__ __launch_bounds__(256)
void split_x_kernel(const float* __restrict__ src)
{
    const int i = blockIdx.x*256 + threadIdx.x;
    const float f = src[i];
    const float h = __bfloat162float(__float2bfloat16(f));
    g_xhi[i] = __float2bfloat16(h);
    g_xlo[i] = __float2bfloat16(f - h);
}

// ---------------- transpose + (optional row scale) + split -------------
template<bool SCALE>
__device__ __forceinline__
void transpose_split_body(const float* __restrict__ in, const float* __restrict__ scale,
                          __nv_bfloat16* __restrict__ hi, __nv_bfloat16* __restrict__ lo,
                          int R, int Ccols)
{
    __shared__ float tile[32][33];
    const int r0 = blockIdx.y*32, c0 = blockIdx.x*32;
    const int tx = threadIdx.x & 31, ty0 = threadIdx.x >> 5;
    #pragma unroll
    for (int p = 0; p < 4; p++) {
        const int ty = ty0 + p*8;
        float vv = in[(size_t)(r0+ty)*Ccols + c0+tx];
        if (SCALE) vv *= scale[r0+ty];
        tile[ty][tx] = vv;
    }
    __syncthreads();
    #pragma unroll
    for (int p = 0; p < 4; p++) {
        const int ty = ty0 + p*8;
        const float f = tile[tx][ty];
        const float h = __bfloat162float(__float2bfloat16(f));
        const size_t o = (size_t)(c0+ty)*R + r0+tx;
        hi[o] = __float2bfloat16(h);
        lo[o] = __float2bfloat16(f - h);
    }
}

__global__ __launch_bounds__(256)
void transpose_fw_kernel(const float* __restrict__ fw)
{
    transpose_split_body<false>(fw, nullptr, g_fwThi, g_fwTlo, DDIM, DDIM);
}
__global__ __launch_bounds__(256)
void transpose_tvt_kernel()
{
    transpose_split_body<true>(g_target, g_v, g_tvthi, g_tvtlo, NTOK, DDIM);
}

// ---------------- pipelined warp-MMA GEMM ------------------------------
// C[M,768] = (Ahi+Alo)@(Bhi+Blo)^T (+bias), 3-pass split.
// BM=64 BN=64 BK=32, 8 warps (2 M x 4 N), warp tile 32x16.
// Double-buffered cp.async: stage = {Ahi(64x40) Alo(64x40) Bhi(64x40) Blo(64x40)} bf16.
#define APAD 40
#define STG_A  5120            // 64*APAD*2 bytes per matrix
#define STG_B0 10240           // B region start
#define STG_BYTES 20480        // per stage
template<bool ADD_BIAS>
__device__ __forceinline__
void gemm_mma_body(const __nv_bfloat16* __restrict__ Ahi, const __nv_bfloat16* __restrict__ Alo,
                   const __nv_bfloat16* __restrict__ Bhi, const __nv_bfloat16* __restrict__ Blo,
                   const float* __restrict__ bias, float* __restrict__ C, int K)
{
    __shared__ __align__(16) char smem_raw[2*STG_BYTES];   // 40 KB static
    const uint32_t sbase = smem_u32(smem_raw);
    const int tid = threadIdx.x;
    const int lane = tid & 31, w = tid >> 5;
    const int wm = w & 1, wn = w >> 1;
    const int m0 = blockIdx.y * 64, n0 = blockIdx.x * 64;

    // per-thread cp.async assignments: 1024 x 16B per chunk, 4 per thread
    uint64_t srcs[4]; uint32_t dsts[4];
    #pragma unroll
    for (int it = 0; it < 4; it++) {
        const int idx = tid + it*256;
        if (idx < 512) {
            const int mat = idx >> 8, r = (idx >> 2) & 63, q = idx & 3;
            srcs[it] = (uint64_t)__cvta_generic_to_global(
                (mat ? Alo : Ahi) + (size_t)(m0+r)*K + q*8);
            dsts[it] = mat*STG_A + r*(APAD*2) + q*16;
        } else {
            const int j = idx - 512;
            const int mat = j >> 8, r = (j >> 2) & 63, q = j & 3;
            srcs[it] = (uint64_t)__cvta_generic_to_global(
                (mat ? Blo : Bhi) + (size_t)(n0+r)*K + q*8);
            dsts[it] = STG_B0 + mat*STG_A + r*(APAD*2) + q*16;
        }
    }

    // ldmatrix offsets (within stage, bytes)
    const uint32_t aRow = wm*32 + (lane & 7) + ((lane >> 3) & 1)*8;
    const uint32_t aCol = ((lane >> 4) & 1)*8;
    const uint32_t bRow = wn*16 + ((lane >> 4) & 1)*8 + (lane & 7);
    const uint32_t bCol = ((lane >> 3) & 1)*8;
    uint32_t aOff[2][2], bOff[2];
    #pragma unroll
    for (int mt = 0; mt < 2; mt++) {
        const uint32_t o = (aRow + mt*16)*(APAD*2) + aCol*2;
        aOff[mt][0] = o; aOff[mt][1] = STG_A + o;
    }
    {
        const uint32_t o = bRow*(APAD*2) + bCol*2;
        bOff[0] = STG_B0 + o; bOff[1] = STG_B0 + STG_A + o;
    }

    float acc[2][2][4] = {};

    // prologue: chunk 0 -> stage 0
    #pragma unroll
    for (int it = 0; it < 4; it++) cp16(sbase + dsts[it], srcs[it]);
    CP_COMMIT();

    const int nch = K >> 5;
    for (int c = 0; c < nch; c++) {
        const uint32_t so = sbase + (uint32_t)(c & 1)*STG_BYTES;
        if (c + 1 < nch) {
            const uint32_t sn = sbase + (uint32_t)((c+1) & 1)*STG_BYTES;
            const uint64_t adv = (uint64_t)(c+1)*64;   // 32 elems * 2B
            #pragma unroll
            for (int it = 0; it < 4; it++) cp16(sn + dsts[it], srcs[it] + adv);
            CP_COMMIT();
            CP_WAIT1();
        } else {
            CP_WAIT0();
        }
        __syncthreads();

        #pragma unroll
        for (int kk = 0; kk < 2; kk++) {
            const uint32_t kb = kk * 32;
            uint32_t Af[2][2][4], Bf[2][4];
            #pragma unroll
            for (int mt = 0; mt < 2; mt++) {
                ldsm_x4(Af[mt][0], so + aOff[mt][0] + kb);
                ldsm_x4(Af[mt][1], so + aOff[mt][1] + kb);
            }
            ldsm_x4(Bf[0], so + bOff[0] + kb);
            ldsm_x4(Bf[1], so + bOff[1] + kb);
            #pragma unroll
            for (int mt = 0; mt < 2; mt++) {
                #pragma unroll
                for (int j = 0; j < 2; j++) {
                    float* cc = acc[mt][j];
                    mma16816(cc, Af[mt][0], &Bf[0][j*2]);   // hi*hi
                    mma16816(cc, Af[mt][0], &Bf[1][j*2]);   // hi*lo
                    mma16816(cc, Af[mt][1], &Bf[0][j*2]);   // lo*hi
                }
            }
        }
        __syncthreads();
    }

    const int g = lane >> 2, tg2 = (lane & 3)*2;
    #pragma unroll
    for (int mt = 0; mt < 2; mt++) {
        const int row = m0 + wm*32 + mt*16 + g;
        #pragma unroll
        for (int j = 0; j < 2; j++) {
            const int col = n0 + wn*16 + j*8 + tg2;
            float b0 = 0.f, b1 = 0.f;
            if (ADD_BIAS) { b0 = bias[col]; b1 = bias[col+1]; }
            *(float2*)&C[(size_t)row*DDIM + col] =
                make_float2(acc[mt][j][0] + b0, acc[mt][j][1] + b1);
            *(float2*)&C[(size_t)(row+8)*DDIM + col] =
                make_float2(acc[mt][j][2] + b0, acc[mt][j][3] + b1);
        }
    }
}

// target = x @ f_w + f_b   (K=768)
__global__ __launch_bounds__(256)
void gemm_target_kernel(const float* __restrict__ fb)
{
    gemm_mma_body<true>(g_xhi, g_xlo, g_fwThi, g_fwTlo, fb, g_target, DDIM);
}
// S = K_eps @ (v*target)   (K=2048)
__global__ __launch_bounds__(256)
void gemm_S_kernel()
{
    gemm_mma_body<false>(g_khi, g_klo, g_tvthi, g_tvtlo, nullptr, g_S, NTOK);
}

// ---------------- d_i = K_eps[i,:] . v + 1e-5 (one warp per row, bf16 K) ----------
__global__ __launch_bounds__(256)
void dvec_kernel()
{
    const int w = blockIdx.x * 8 + (threadIdx.x >> 5);
    const int lane = threadIdx.x & 31;
    const size_t base = (size_t)w * NTOK;
    float s = 0.f;
    for (int j = lane*2; j < NTOK; j += 64) {
        __nv_bfloat162 h2 = *(const __nv_bfloat162*)&g_khi[base + j];
        __nv_bfloat162 l2 = *(const __nv_bfloat162*)&g_klo[base + j];
        float2 vv = *(const float2*)&g_v[j];
        s += (__bfloat162float(h2.x) + __bfloat162float(l2.x)) * vv.x
           + (__bfloat162float(h2.y) + __bfloat162float(l2.y)) * vv.y;
    }
    #pragma unroll
    for (int off = 16; off; off >>= 1) s += __shfl_down_sync(0xffffffffu, s, off);
    if (lane == 0) g_d[w] = s + 1e-5f;
}

// ---------------- final: combine + LayerNorm(768) ----------------
__global__ __launch_bounds__(256)
void final_kernel(const float* __restrict__ x, const float* __restrict__ dtp,
                  const float* __restrict__ g2, const float* __restrict__ b2,
                  float* __restrict__ out)
{
    const int i = blockIdx.x;
    const int t = threadIdx.x;
    const float dtv = dtp[0];
    const float invd = (1.f/EPSILON_) / g_d[i];

    float vals[3];
    float sum = 0.f, sq = 0.f;
    #pragma unroll
    for (int c = 0; c < 3; c++) {
        const int d = t + c*256;
        const float tg = g_target[(size_t)i*DDIM + d];
        const float tt = dtv * (invd * g_S[(size_t)i*DDIM + d] - tg);
        const float t2 = 0.7f * x[(size_t)i*DDIM + d] + 0.3f*(tg + 2.f*tt);
        vals[c] = t2; sum += t2; sq += t2*t2;
    }
    __shared__ float rsm[256], rqm[256];
    __shared__ float mu_s, is_s;
    rsm[t] = sum; rqm[t] = sq;
    __syncthreads();
    for (int s = 128; s > 0; s >>= 1) {
        if (t < s) { rsm[t] += rsm[t+s]; rqm[t] += rqm[t+s]; }
        __syncthreads();
    }
    if (t == 0) {
        float mu = rsm[0] * (1.f/DDIM);
        float var = rqm[0] * (1.f/DDIM) - mu*mu;
        mu_s = mu; is_s = rsqrtf(var + 1e-5f);
    }
    __syncthreads();
    #pragma unroll
    for (int c = 0; c < 3; c++) {
        const int d = t + c*256;
        out[(size_t)i*DDIM + d] = (vals[c]-mu_s)*is_s*g2[d] + b2[d];
    }
}

// ---------------- launch (pure kernel launches; nothing else) ----------------
extern "C" void kernel_launch(void* const* d_in, const int* in_sizes, int n_in,
                              void* d_out, int out_size)
{
    const float* x      = (const float*)d_in[0];
    const float* proj_w = (const float*)d_in[1];
    const float* proj_b = (const float*)d_in[2];
    const float* ln1_g  = (const float*)d_in[3];
    const float* ln1_b  = (const float*)d_in[4];
    const float* pi_w1  = (const float*)d_in[5];
    const float* pi_b1  = (const float*)d_in[6];
    const float* pi_w2  = (const float*)d_in[7];
    const float* pi_b2  = (const float*)d_in[8];
    const float* dt     = (const float*)d_in[9];
    const float* f_w    = (const float*)d_in[10];
    const float* f_b    = (const float*)d_in[11];
    const float* ln2_g  = (const float*)d_in[12];
    const float* ln2_b  = (const float*)d_in[13];
    float* out = (float*)d_out;

    proj_pi_kernel<<<NTOK/4, 256>>>(x, proj_w, proj_b, ln1_g, ln1_b,
                                    pi_w1, pi_b1, pi_w2, pi_b2);
    split_x_kernel<<<(NTOK*DDIM)/256, 256>>>(x);
    transpose_fw_kernel<<<dim3(DDIM/32, DDIM/32), 256>>>(f_w);
    keps_kernel<<<dim3(32,32), 256>>>();
    v_kernel<<<8, 256>>>();
    gemm_target_kernel<<<dim3(DDIM/64, NTOK/64), 256>>>(f_b);
    transpose_tvt_kernel<<<dim3(DDIM/32, NTOK/32), 256>>>();
    dvec_kernel<<<NTOK/8, 256>>>();
    gemm_S_kernel<<<dim3(DDIM/64, NTOK/64), 256>>>();
    final_kernel<<<NTOK, 256>>>(x, dt, ln2_g, ln2_b, out);
}

// round 6
// speedup vs baseline: 5.1220x; 1.3796x over previous
#include <cuda_runtime.h>
#include <cuda_bf16.h>
#include <cuda_fp16.h>
#include <cstdint>

#define NTOK 2048
#define DDIM 768
#define LDIM 16
#define EPSILON_ 0.3f
#define CEXP (1.0f/(4.0f*EPSILON_))

// ---------------- scratch (no allocations allowed) ----------------
__device__ float g_xproj[NTOK*LDIM];
__device__ float g_sqn[NTOK];
__device__ float g_pi[NTOK];
__device__ __half g_kf16[(size_t)NTOK*NTOK];          // 8.4 MB, K_eps fp16
__device__ float g_qpart[32*NTOK];
__device__ float g_v[NTOK];
__device__ float g_d[NTOK];
__device__ float g_target[NTOK*DDIM];
__device__ float g_S[NTOK*DDIM];
__device__ __nv_bfloat16 g_xhi[NTOK*DDIM];
__device__ __nv_bfloat16 g_xlo[NTOK*DDIM];
__device__ __nv_bfloat16 g_fwThi[DDIM*DDIM];          // f_w^T : [n, k]
__device__ __nv_bfloat16 g_fwTlo[DDIM*DDIM];
__device__ __half g_tvt16[DDIM*NTOK];                 // (v*target)^T fp16 : [n, k]

// ---------------- warp-MMA / cp.async helpers (baseline PTX) ----------
__device__ __forceinline__ uint32_t smem_u32(const void* p) {
    uint32_t a;
    asm("{ .reg .u64 t; cvta.to.shared.u64 t, %1; cvt.u32.u64 %0, t; }" : "=r"(a) : "l"(p));
    return a;
}
__device__ __forceinline__ void ldsm_x4(uint32_t* r, uint32_t addr) {
    asm volatile("ldmatrix.sync.aligned.m8n8.x4.shared.b16 {%0,%1,%2,%3}, [%4];"
        : "=r"(r[0]), "=r"(r[1]), "=r"(r[2]), "=r"(r[3]) : "r"(addr));
}
__device__ __forceinline__ void mma16816bf(float* c, const uint32_t* a, const uint32_t* b) {
    asm volatile("mma.sync.aligned.m16n8k16.row.col.f32.bf16.bf16.f32 "
        "{%0,%1,%2,%3}, {%4,%5,%6,%7}, {%8,%9}, {%0,%1,%2,%3};"
        : "+f"(c[0]), "+f"(c[1]), "+f"(c[2]), "+f"(c[3])
        : "r"(a[0]), "r"(a[1]), "r"(a[2]), "r"(a[3]), "r"(b[0]), "r"(b[1]));
}
__device__ __forceinline__ void mma16816h(float* c, const uint32_t* a, const uint32_t* b) {
    asm volatile("mma.sync.aligned.m16n8k16.row.col.f32.f16.f16.f32 "
        "{%0,%1,%2,%3}, {%4,%5,%6,%7}, {%8,%9}, {%0,%1,%2,%3};"
        : "+f"(c[0]), "+f"(c[1]), "+f"(c[2]), "+f"(c[3])
        : "r"(a[0]), "r"(a[1]), "r"(a[2]), "r"(a[3]), "r"(b[0]), "r"(b[1]));
}
__device__ __forceinline__ void cp16(uint32_t dst, uint64_t gsrc) {
    asm volatile("cp.async.ca.shared.global [%0], [%1], 16;" :: "r"(dst), "l"(gsrc) : "memory");
}
#define CP_COMMIT() asm volatile("cp.async.commit_group;" ::: "memory")
#define CP_WAIT1()  asm volatile("cp.async.wait_group 1;" ::: "memory")
#define CP_WAIT0()  asm volatile("cp.async.wait_group 0;" ::: "memory")

// ---------------- kernel A: proj -> LN(16) -> ReLU, + pi head + x split ---------
__global__ __launch_bounds__(256)
void proj_pi_kernel(const float* __restrict__ x, const float* __restrict__ pw,
                    const float* __restrict__ pb, const float* __restrict__ g1,
                    const float* __restrict__ b1, const float* __restrict__ w1,
                    const float* __restrict__ bb1, const float* __restrict__ w2,
                    const float* __restrict__ bb2)
{
    const int i0 = blockIdx.x * 4;
    const int t = threadIdx.x;
    const int lane = t & 31, wid = t >> 5;
    __shared__ float xs[4][DDIM];
    __shared__ float part[256];
    __shared__ float yv[4][LDIM];
    __shared__ float xp[4][LDIM];
    __shared__ float red[4][8];

    #pragma unroll
    for (int r = 0; r < 4; r++)
        for (int d = t; d < DDIM; d += 256) xs[r][d] = x[(size_t)(i0+r)*DDIM + d];
    __syncthreads();

    // fused x -> bf16 hi/lo split
    #pragma unroll
    for (int r = 0; r < 4; r++)
        for (int d = t; d < DDIM; d += 256) {
            const float f = xs[r][d];
            const float h = __bfloat162float(__float2bfloat16(f));
            g_xhi[(size_t)(i0+r)*DDIM + d] = __float2bfloat16(h);
            g_xlo[(size_t)(i0+r)*DDIM + d] = __float2bfloat16(f - h);
        }

    // proj: y[r][l] = x_row[r] . proj_w[:,l]
    const int l = t & 15, g = t >> 4;
    float accs[4] = {};
    for (int d = g; d < DDIM; d += 16) {
        const float w = pw[d*LDIM + l];
        accs[0] += xs[0][d]*w; accs[1] += xs[1][d]*w;
        accs[2] += xs[2][d]*w; accs[3] += xs[3][d]*w;
    }
    #pragma unroll
    for (int r = 0; r < 4; r++) {
        __syncthreads();
        part[t] = accs[r];
        __syncthreads();
        if (t < LDIM) {
            float s = 0.f;
            #pragma unroll
            for (int gg = 0; gg < 16; gg++) s += part[gg*16 + t];
            yv[r][t] = s + pb[t];
        }
    }
    __syncthreads();
    // LN(16) + ReLU per row: threads 0..3
    if (t < 4) {
        float mu = 0.f;
        #pragma unroll
        for (int q = 0; q < LDIM; q++) mu += yv[t][q];
        mu *= (1.f/LDIM);
        float var = 0.f;
        #pragma unroll
        for (int q = 0; q < LDIM; q++) { float dd = yv[t][q]-mu; var += dd*dd; }
        var *= (1.f/LDIM);
        const float is = rsqrtf(var + 1e-5f);
        float sq = 0.f;
        #pragma unroll
        for (int q = 0; q < LDIM; q++) {
            float vv = fmaxf((yv[t][q]-mu)*is*g1[q] + b1[q], 0.f);
            xp[t][q] = vv; sq += vv*vv;
        }
        g_sqn[i0+t] = sq;
    }
    __syncthreads();
    if (t < 64) g_xproj[(i0 + (t>>4))*LDIM + (t&15)] = xp[t>>4][t&15];

    // pi head
    float pacc[4] = {};
    for (int dp = t; dp < DDIM; dp += 256) {
        const float bb = bb1[dp], wo = w2[dp];
        float wc[16];
        #pragma unroll
        for (int q = 0; q < 16; q++) wc[q] = w1[q*DDIM + dp];
        #pragma unroll
        for (int r = 0; r < 4; r++) {
            float h = bb;
            #pragma unroll
            for (int q = 0; q < 16; q++) h += xp[r][q]*wc[q];
            h = fmaxf(h, 0.f);
            pacc[r] += h * wo;
        }
    }
    #pragma unroll
    for (int r = 0; r < 4; r++) {
        float v = pacc[r];
        #pragma unroll
        for (int off = 16; off; off >>= 1) v += __shfl_down_sync(0xffffffffu, v, off);
        if (lane == 0) red[r][wid] = v;
    }
    __syncthreads();
    if (t < 4) {
        float s = 0.f;
        #pragma unroll
        for (int q = 0; q < 8; q++) s += red[t][q];
        g_pi[i0+t] = 1.f/(1.f + __expf(-(s + bb2[0])));
    }
}

// ---------------- kernel B: K_eps tile (64x64) -> fp16 + partial rowsums ----
__global__ __launch_bounds__(256)
void keps_kernel()
{
    const int i0 = blockIdx.y * 64, j0 = blockIdx.x * 64;
    const int t = threadIdx.x;
    const int tx = t & 15, ty = t >> 4;
    __shared__ float xi[64][16];
    __shared__ float xjT[16][64];
    __shared__ float si[64], sj[64];
    __shared__ float rs[64][17];
    {
        const int r = t >> 2, c = (t & 3) * 4;
        float4 a = *(const float4*)&g_xproj[(i0 + r)*LDIM + c];
        *(float4*)&xi[r][c] = a;
        float4 b = *(const float4*)&g_xproj[(j0 + r)*LDIM + c];
        xjT[c+0][r] = b.x; xjT[c+1][r] = b.y; xjT[c+2][r] = b.z; xjT[c+3][r] = b.w;
    }
    if (t < 64) { si[t] = g_sqn[i0+t]; sj[t] = g_sqn[j0+t]; }
    __syncthreads();

    float bj[4][16];
    float sjr[4];
    #pragma unroll
    for (int n = 0; n < 4; n++) {
        const int jj = tx*4 + n;
        sjr[n] = sj[jj];
        #pragma unroll
        for (int q = 0; q < 16; q++) bj[n][q] = xjT[q][jj];
    }
    #pragma unroll
    for (int m = 0; m < 4; m++) {
        const int ii = ty*4 + m;
        float a[16];
        #pragma unroll
        for (int q = 0; q < 16; q++) a[q] = xi[ii][q];
        const float sii = si[ii];
        float o[4]; float rsum = 0.f;
        #pragma unroll
        for (int n = 0; n < 4; n++) {
            float dot = 0.f;
            #pragma unroll
            for (int q = 0; q < 16; q++) dot += a[q]*bj[n][q];
            float kv = __expf(-CEXP*(sii + sjr[n] - 2.f*dot));
            o[n] = kv; rsum += kv;
        }
        const size_t base = (size_t)(i0+ii)*NTOK + j0 + tx*4;
        *(__half2*)&g_kf16[base]   = __floats2half2_rn(o[0], o[1]);
        *(__half2*)&g_kf16[base+2] = __floats2half2_rn(o[2], o[3]);
        rs[ii][tx] = rsum;
    }
    __syncthreads();
    if (t < 64) {
        float s = 0.f;
        #pragma unroll
        for (int c = 0; c < 16; c++) s += rs[t][c];
        g_qpart[blockIdx.x*NTOK + i0 + t] = s;
    }
}

// ---------------- kernel C: v = pi / q_tilde ----------------
__global__ void v_kernel()
{
    const int j = blockIdx.x*256 + threadIdx.x;
    if (j < NTOK) {
        float q = 0.f;
        #pragma unroll
        for (int p = 0; p < 32; p++) q += g_qpart[p*NTOK + j];
        g_v[j] = g_pi[j] / q;
    }
}

// ---------------- transpose + split bf16 (f_w^T) -------------
__global__ __launch_bounds__(256)
void transpose_fw_kernel(const float* __restrict__ in)
{
    __shared__ float tile[32][33];
    const int r0 = blockIdx.y*32, c0 = blockIdx.x*32;
    const int tx = threadIdx.x & 31, ty0 = threadIdx.x >> 5;
    #pragma unroll
    for (int p = 0; p < 4; p++) {
        const int ty = ty0 + p*8;
        tile[ty][tx] = in[(size_t)(r0+ty)*DDIM + c0+tx];
    }
    __syncthreads();
    #pragma unroll
    for (int p = 0; p < 4; p++) {
        const int ty = ty0 + p*8;
        const float f = tile[tx][ty];
        const float h = __bfloat162float(__float2bfloat16(f));
        const size_t o = (size_t)(c0+ty)*DDIM + r0+tx;
        g_fwThi[o] = __float2bfloat16(h);
        g_fwTlo[o] = __float2bfloat16(f - h);
    }
}

// ---------------- transpose + row scale -> fp16 ((v*target)^T) -------------
__global__ __launch_bounds__(256)
void transpose_tvt_kernel()
{
    __shared__ float tile[32][33];
    const int r0 = blockIdx.y*32, c0 = blockIdx.x*32;
    const int tx = threadIdx.x & 31, ty0 = threadIdx.x >> 5;
    #pragma unroll
    for (int p = 0; p < 4; p++) {
        const int ty = ty0 + p*8;
        tile[ty][tx] = g_target[(size_t)(r0+ty)*DDIM + c0+tx] * g_v[r0+ty];
    }
    __syncthreads();
    #pragma unroll
    for (int p = 0; p < 4; p++) {
        const int ty = ty0 + p*8;
        g_tvt16[(size_t)(c0+ty)*NTOK + r0+tx] = __float2half(tile[tx][ty]);
    }
}

// ---------------- bf16 3-pass pipelined GEMM (target = x @ f_w + f_b) -----------
// BM=64 BN=64 BK=32, 8 warps (2 M x 4 N), warp tile 32x16, double-buffered.
#define APAD 40
#define STG_A  5120
#define STG_B0 10240
#define STG_BYTES 20480
__global__ __launch_bounds__(256)
void gemm_target_kernel(const float* __restrict__ bias)
{
    const __nv_bfloat16* __restrict__ Ahi = g_xhi;
    const __nv_bfloat16* __restrict__ Alo = g_xlo;
    const __nv_bfloat16* __restrict__ Bhi = g_fwThi;
    const __nv_bfloat16* __restrict__ Blo = g_fwTlo;
    const int K = DDIM;
    __shared__ __align__(16) char smem_raw[2*STG_BYTES];
    const uint32_t sbase = smem_u32(smem_raw);
    const int tid = threadIdx.x;
    const int lane = tid & 31, w = tid >> 5;
    const int wm = w & 1, wn = w >> 1;
    const int m0 = blockIdx.y * 64, n0 = blockIdx.x * 64;

    uint64_t srcs[4]; uint32_t dsts[4];
    #pragma unroll
    for (int it = 0; it < 4; it++) {
        const int idx = tid + it*256;
        if (idx < 512) {
            const int mat = idx >> 8, r = (idx >> 2) & 63, q = idx & 3;
            srcs[it] = (uint64_t)__cvta_generic_to_global(
                (mat ? Alo : Ahi) + (size_t)(m0+r)*K + q*8);
            dsts[it] = mat*STG_A + r*(APAD*2) + q*16;
        } else {
            const int j = idx - 512;
            const int mat = j >> 8, r = (j >> 2) & 63, q = j & 3;
            srcs[it] = (uint64_t)__cvta_generic_to_global(
                (mat ? Blo : Bhi) + (size_t)(n0+r)*K + q*8);
            dsts[it] = STG_B0 + mat*STG_A + r*(APAD*2) + q*16;
        }
    }

    const uint32_t aRow = wm*32 + (lane & 7) + ((lane >> 3) & 1)*8;
    const uint32_t aCol = ((lane >> 4) & 1)*8;
    const uint32_t bRow = wn*16 + ((lane >> 4) & 1)*8 + (lane & 7);
    const uint32_t bCol = ((lane >> 3) & 1)*8;
    uint32_t aOff[2][2], bOff[2];
    #pragma unroll
    for (int mt = 0; mt < 2; mt++) {
        const uint32_t o = (aRow + mt*16)*(APAD*2) + aCol*2;
        aOff[mt][0] = o; aOff[mt][1] = STG_A + o;
    }
    {
        const uint32_t o = bRow*(APAD*2) + bCol*2;
        bOff[0] = STG_B0 + o; bOff[1] = STG_B0 + STG_A + o;
    }

    float acc[2][2][4] = {};

    #pragma unroll
    for (int it = 0; it < 4; it++) cp16(sbase + dsts[it], srcs[it]);
    CP_COMMIT();

    const int nch = K >> 5;
    for (int c = 0; c < nch; c++) {
        const uint32_t so = sbase + (uint32_t)(c & 1)*STG_BYTES;
        if (c + 1 < nch) {
            const uint32_t sn = sbase + (uint32_t)((c+1) & 1)*STG_BYTES;
            const uint64_t adv = (uint64_t)(c+1)*64;
            #pragma unroll
            for (int it = 0; it < 4; it++) cp16(sn + dsts[it], srcs[it] + adv);
            CP_COMMIT();
            CP_WAIT1();
        } else {
            CP_WAIT0();
        }
        __syncthreads();

        #pragma unroll
        for (int kk = 0; kk < 2; kk++) {
            const uint32_t kb = kk * 32;
            uint32_t Af[2][2][4], Bf[2][4];
            #pragma unroll
            for (int mt = 0; mt < 2; mt++) {
                ldsm_x4(Af[mt][0], so + aOff[mt][0] + kb);
                ldsm_x4(Af[mt][1], so + aOff[mt][1] + kb);
            }
            ldsm_x4(Bf[0], so + bOff[0] + kb);
            ldsm_x4(Bf[1], so + bOff[1] + kb);
            #pragma unroll
            for (int mt = 0; mt < 2; mt++) {
                #pragma unroll
                for (int j = 0; j < 2; j++) {
                    float* cc = acc[mt][j];
                    mma16816bf(cc, Af[mt][0], &Bf[0][j*2]);
                    mma16816bf(cc, Af[mt][0], &Bf[1][j*2]);
                    mma16816bf(cc, Af[mt][1], &Bf[0][j*2]);
                }
            }
        }
        __syncthreads();
    }

    const int g = lane >> 2, tg2 = (lane & 3)*2;
    #pragma unroll
    for (int mt = 0; mt < 2; mt++) {
        const int row = m0 + wm*32 + mt*16 + g;
        #pragma unroll
        for (int j = 0; j < 2; j++) {
            const int col = n0 + wn*16 + j*8 + tg2;
            const float b0 = bias[col], b1 = bias[col+1];
            *(float2*)&g_target[(size_t)row*DDIM + col] =
                make_float2(acc[mt][j][0] + b0, acc[mt][j][1] + b1);
            *(float2*)&g_target[(size_t)(row+8)*DDIM + col] =
                make_float2(acc[mt][j][2] + b0, acc[mt][j][3] + b1);
        }
    }
}

// ---------------- fp16 single-pass pipelined GEMM (S = K_eps @ (v*target)) -------
// BM=64 BN=64 BK=64, 8 warps (2 M x 4 N), warp tile 32x16, double-buffered.
#define FAPAD 72
#define FROWB (FAPAD*2)        // 144 bytes per row
#define FSTG_A 9216            // 64*144
#define FSTG_B0 9216
#define FSTG_BYTES 18432
__global__ __launch_bounds__(256)
void gemm_S_kernel()
{
    const __half* __restrict__ A = g_kf16;
    const __half* __restrict__ B = g_tvt16;
    const int K = NTOK;
    __shared__ __align__(16) char smem_raw[2*FSTG_BYTES];   // 36.9 KB
    const uint32_t sbase = smem_u32(smem_raw);
    const int tid = threadIdx.x;
    const int lane = tid & 31, w = tid >> 5;
    const int wm = w & 1, wn = w >> 1;
    const int m0 = blockIdx.y * 64, n0 = blockIdx.x * 64;

    // per-thread cp.async: 1024 x 16B per chunk, 4 per thread
    uint64_t srcs[4]; uint32_t dsts[4];
    #pragma unroll
    for (int it = 0; it < 4; it++) {
        const int idx = tid + it*256;
        if (idx < 512) {
            const int r = idx >> 3, q = idx & 7;
            srcs[it] = (uint64_t)__cvta_generic_to_global(A + (size_t)(m0+r)*K + q*8);
            dsts[it] = r*FROWB + q*16;
        } else {
            const int j = idx - 512;
            const int r = j >> 3, q = j & 7;
            srcs[it] = (uint64_t)__cvta_generic_to_global(B + (size_t)(n0+r)*K + q*8);
            dsts[it] = FSTG_B0 + r*FROWB + q*16;
        }
    }

    const uint32_t aRow = wm*32 + (lane & 7) + ((lane >> 3) & 1)*8;
    const uint32_t aCol = ((lane >> 4) & 1)*8;
    const uint32_t bRow = wn*16 + ((lane >> 4) & 1)*8 + (lane & 7);
    const uint32_t bCol = ((lane >> 3) & 1)*8;
    uint32_t aOff[2], bOff;
    #pragma unroll
    for (int mt = 0; mt < 2; mt++)
        aOff[mt] = (aRow + mt*16)*FROWB + aCol*2;
    bOff = FSTG_B0 + bRow*FROWB + bCol*2;

    float acc[2][2][4] = {};

    #pragma unroll
    for (int it = 0; it < 4; it++) cp16(sbase + dsts[it], srcs[it]);
    CP_COMMIT();

    const int nch = K >> 6;
    for (int c = 0; c < nch; c++) {
        const uint32_t so = sbase + (uint32_t)(c & 1)*FSTG_BYTES;
        if (c + 1 < nch) {
            const uint32_t sn = sbase + (uint32_t)((c+1) & 1)*FSTG_BYTES;
            const uint64_t adv = (uint64_t)(c+1)*128;   // 64 elems * 2B
            #pragma unroll
            for (int it = 0; it < 4; it++) cp16(sn + dsts[it], srcs[it] + adv);
            CP_COMMIT();
            CP_WAIT1();
        } else {
            CP_WAIT0();
        }
        __syncthreads();

        #pragma unroll
        for (int kk = 0; kk < 4; kk++) {
            const uint32_t kb = kk * 32;
            uint32_t Af[2][4], Bf[4];
            ldsm_x4(Af[0], so + aOff[0] + kb);
            ldsm_x4(Af[1], so + aOff[1] + kb);
            ldsm_x4(Bf, so + bOff + kb);
            #pragma unroll
            for (int mt = 0; mt < 2; mt++) {
                mma16816h(acc[mt][0], Af[mt], &Bf[0]);
                mma16816h(acc[mt][1], Af[mt], &Bf[2]);
            }
        }
        __syncthreads();
    }

    const int g = lane >> 2, tg2 = (lane & 3)*2;
    #pragma unroll
    for (int mt = 0; mt < 2; mt++) {
        const int row = m0 + wm*32 + mt*16 + g;
        #pragma unroll
        for (int j = 0; j < 2; j++) {
            const int col = n0 + wn*16 + j*8 + tg2;
            *(float2*)&g_S[(size_t)row*DDIM + col] =
                make_float2(acc[mt][j][0], acc[mt][j][1]);
            *(float2*)&g_S[(size_t)(row+8)*DDIM + col] =
                make_float2(acc[mt][j][2], acc[mt][j][3]);
        }
    }
}

// ---------------- d_i = K_eps[i,:] . v + 1e-5 (one warp per row, fp16 K) ----------
__global__ __launch_bounds__(256)
void dvec_kernel()
{
    const int w = blockIdx.x * 8 + (threadIdx.x >> 5);
    const int lane = threadIdx.x & 31;
    const size_t base = (size_t)w * NTOK;
    float s = 0.f;
    for (int j = lane*4; j < NTOK; j += 128) {
        __half2 k0 = *(const __half2*)&g_kf16[base + j];
        __half2 k1 = *(const __half2*)&g_kf16[base + j + 2];
        float4 vv = *(const float4*)&g_v[j];
        const float2 f0 = __half22float2(k0), f1 = __half22float2(k1);
        s += f0.x*vv.x + f0.y*vv.y + f1.x*vv.z + f1.y*vv.w;
    }
    #pragma unroll
    for (int off = 16; off; off >>= 1) s += __shfl_down_sync(0xffffffffu, s, off);
    if (lane == 0) g_d[w] = s + 1e-5f;
}

// ---------------- final: combine + LayerNorm(768) ----------------
__global__ __launch_bounds__(256)
void final_kernel(const float* __restrict__ x, const float* __restrict__ dtp,
                  const float* __restrict__ g2, const float* __restrict__ b2,
                  float* __restrict__ out)
{
    const int i = blockIdx.x;
    const int t = threadIdx.x;
    const float dtv = dtp[0];
    const float invd = (1.f/EPSILON_) / g_d[i];

    float vals[3];
    float sum = 0.f, sq = 0.f;
    #pragma unroll
    for (int c = 0; c < 3; c++) {
        const int d = t + c*256;
        const float tg = g_target[(size_t)i*DDIM + d];
        const float tt = dtv * (invd * g_S[(size_t)i*DDIM + d] - tg);
        const float t2 = 0.7f * x[(size_t)i*DDIM + d] + 0.3f*(tg + 2.f*tt);
        vals[c] = t2; sum += t2; sq += t2*t2;
    }
    __shared__ float rsm[256], rqm[256];
    __shared__ float mu_s, is_s;
    rsm[t] = sum; rqm[t] = sq;
    __syncthreads();
    for (int s = 128; s > 0; s >>= 1) {
        if (t < s) { rsm[t] += rsm[t+s]; rqm[t] += rqm[t+s]; }
        __syncthreads();
    }
    if (t == 0) {
        float mu = rsm[0] * (1.f/DDIM);
        float var = rqm[0] * (1.f/DDIM) - mu*mu;
        mu_s = mu; is_s = rsqrtf(var + 1e-5f);
    }
    __syncthreads();
    #pragma unroll
    for (int c = 0; c < 3; c++) {
        const int d = t + c*256;
        out[(size_t)i*DDIM + d] = (vals[c]-mu_s)*is_s*g2[d] + b2[d];
    }
}

// ---------------- launch (pure kernel launches; nothing else) ----------------
extern "C" void kernel_launch(void* const* d_in, const int* in_sizes, int n_in,
                              void* d_out, int out_size)
{
    const float* x      = (const float*)d_in[0];
    const float* proj_w = (const float*)d_in[1];
    const float* proj_b = (const float*)d_in[2];
    const float* ln1_g  = (const float*)d_in[3];
    const float* ln1_b  = (const float*)d_in[4];
    const float* pi_w1  = (const float*)d_in[5];
    const float* pi_b1  = (const float*)d_in[6];
    const float* pi_w2  = (const float*)d_in[7];
    const float* pi_b2  = (const float*)d_in[8];
    const float* dt     = (const float*)d_in[9];
    const float* f_w    = (const float*)d_in[10];
    const float* f_b    = (const float*)d_in[11];
    const float* ln2_g  = (const float*)d_in[12];
    const float* ln2_b  = (const float*)d_in[13];
    float* out = (float*)d_out;

    proj_pi_kernel<<<NTOK/4, 256>>>(x, proj_w, proj_b, ln1_g, ln1_b,
                                    pi_w1, pi_b1, pi_w2, pi_b2);
    transpose_fw_kernel<<<dim3(DDIM/32, DDIM/32), 256>>>(f_w);
    keps_kernel<<<dim3(32,32), 256>>>();
    v_kernel<<<8, 256>>>();
    gemm_target_kernel<<<dim3(DDIM/64, NTOK/64), 256>>>(f_b);
    transpose_tvt_kernel<<<dim3(DDIM/32, NTOK/32), 256>>>();
    dvec_kernel<<<NTOK/8, 256>>>();
    gemm_S_kernel<<<dim3(DDIM/64, NTOK/64), 256>>>();
    final_kernel<<<NTOK, 256>>>(x, dt, ln2_g, ln2_b, out);
}

// round 7
// speedup vs baseline: 5.8075x; 1.1338x over previous
#include <cuda_runtime.h>
#include <cuda_fp16.h>
#include <cstdint>

#define NTOK 2048
#define DDIM 768
#define LDIM 16
#define EPSILON_ 0.3f
#define CEXP (1.0f/(4.0f*EPSILON_))

// ---------------- scratch (no allocations allowed) ----------------
__device__ float g_xproj[NTOK*LDIM];
__device__ float g_sqn[NTOK];
__device__ float g_pi[NTOK];
__device__ __half g_kf16[(size_t)NTOK*NTOK];          // 8.4 MB, K_eps fp16
__device__ float g_qpart[NTOK*32];                    // [i][p] transposed partials
__device__ float g_v[NTOK];
__device__ float g_target[NTOK*DDIM];
__device__ float g_S[NTOK*DDIM];
__device__ __half g_x16[NTOK*DDIM];                   // x fp16
__device__ __half g_fwT16[DDIM*DDIM];                 // f_w^T fp16 : [n, k]
__device__ __half g_tvt16[DDIM*NTOK];                 // (v*target)^T fp16 : [n, k]

// ---------------- warp-MMA / cp.async helpers (baseline PTX) ----------
__device__ __forceinline__ uint32_t smem_u32(const void* p) {
    uint32_t a;
    asm("{ .reg .u64 t; cvta.to.shared.u64 t, %1; cvt.u32.u64 %0, t; }" : "=r"(a) : "l"(p));
    return a;
}
__device__ __forceinline__ void ldsm_x4(uint32_t* r, uint32_t addr) {
    asm volatile("ldmatrix.sync.aligned.m8n8.x4.shared.b16 {%0,%1,%2,%3}, [%4];"
        : "=r"(r[0]), "=r"(r[1]), "=r"(r[2]), "=r"(r[3]) : "r"(addr));
}
__device__ __forceinline__ void mma16816h(float* c, const uint32_t* a, const uint32_t* b) {
    asm volatile("mma.sync.aligned.m16n8k16.row.col.f32.f16.f16.f32 "
        "{%0,%1,%2,%3}, {%4,%5,%6,%7}, {%8,%9}, {%0,%1,%2,%3};"
        : "+f"(c[0]), "+f"(c[1]), "+f"(c[2]), "+f"(c[3])
        : "r"(a[0]), "r"(a[1]), "r"(a[2]), "r"(a[3]), "r"(b[0]), "r"(b[1]));
}
__device__ __forceinline__ void cp16(uint32_t dst, uint64_t gsrc) {
    asm volatile("cp.async.ca.shared.global [%0], [%1], 16;" :: "r"(dst), "l"(gsrc) : "memory");
}
#define CP_COMMIT() asm volatile("cp.async.commit_group;" ::: "memory")
#define CP_WAIT1()  asm volatile("cp.async.wait_group 1;" ::: "memory")
#define CP_WAIT0()  asm volatile("cp.async.wait_group 0;" ::: "memory")

// ---------------- kernel A: proj -> LN(16) -> ReLU, + pi head + x fp16 ---------
__global__ __launch_bounds__(256)
void proj_pi_kernel(const float* __restrict__ x, const float* __restrict__ pw,
                    const float* __restrict__ pb, const float* __restrict__ g1,
                    const float* __restrict__ b1, const float* __restrict__ w1,
                    const float* __restrict__ bb1, const float* __restrict__ w2,
                    const float* __restrict__ bb2)
{
    const int i0 = blockIdx.x * 4;
    const int t = threadIdx.x;
    const int lane = t & 31, wid = t >> 5;
    __shared__ float xs[4][DDIM];
    __shared__ float part[256];
    __shared__ float yv[4][LDIM];
    __shared__ float xp[4][LDIM];
    __shared__ float red[4][8];

    #pragma unroll
    for (int r = 0; r < 4; r++)
        for (int d = t; d < DDIM; d += 256) xs[r][d] = x[(size_t)(i0+r)*DDIM + d];
    __syncthreads();

    // fused x -> fp16
    #pragma unroll
    for (int r = 0; r < 4; r++)
        for (int d = t; d < DDIM; d += 256)
            g_x16[(size_t)(i0+r)*DDIM + d] = __float2half(xs[r][d]);

    // proj: y[r][l] = x_row[r] . proj_w[:,l]
    const int l = t & 15, g = t >> 4;
    float accs[4] = {};
    for (int d = g; d < DDIM; d += 16) {
        const float w = pw[d*LDIM + l];
        accs[0] += xs[0][d]*w; accs[1] += xs[1][d]*w;
        accs[2] += xs[2][d]*w; accs[3] += xs[3][d]*w;
    }
    #pragma unroll
    for (int r = 0; r < 4; r++) {
        __syncthreads();
        part[t] = accs[r];
        __syncthreads();
        if (t < LDIM) {
            float s = 0.f;
            #pragma unroll
            for (int gg = 0; gg < 16; gg++) s += part[gg*16 + t];
            yv[r][t] = s + pb[t];
        }
    }
    __syncthreads();
    if (t < 4) {
        float mu = 0.f;
        #pragma unroll
        for (int q = 0; q < LDIM; q++) mu += yv[t][q];
        mu *= (1.f/LDIM);
        float var = 0.f;
        #pragma unroll
        for (int q = 0; q < LDIM; q++) { float dd = yv[t][q]-mu; var += dd*dd; }
        var *= (1.f/LDIM);
        const float is = rsqrtf(var + 1e-5f);
        float sq = 0.f;
        #pragma unroll
        for (int q = 0; q < LDIM; q++) {
            float vv = fmaxf((yv[t][q]-mu)*is*g1[q] + b1[q], 0.f);
            xp[t][q] = vv; sq += vv*vv;
        }
        g_sqn[i0+t] = sq;
    }
    __syncthreads();
    if (t < 64) g_xproj[(i0 + (t>>4))*LDIM + (t&15)] = xp[t>>4][t&15];

    float pacc[4] = {};
    for (int dp = t; dp < DDIM; dp += 256) {
        const float bb = bb1[dp], wo = w2[dp];
        float wc[16];
        #pragma unroll
        for (int q = 0; q < 16; q++) wc[q] = w1[q*DDIM + dp];
        #pragma unroll
        for (int r = 0; r < 4; r++) {
            float h = bb;
            #pragma unroll
            for (int q = 0; q < 16; q++) h += xp[r][q]*wc[q];
            h = fmaxf(h, 0.f);
            pacc[r] += h * wo;
        }
    }
    #pragma unroll
    for (int r = 0; r < 4; r++) {
        float v = pacc[r];
        #pragma unroll
        for (int off = 16; off; off >>= 1) v += __shfl_down_sync(0xffffffffu, v, off);
        if (lane == 0) red[r][wid] = v;
    }
    __syncthreads();
    if (t < 4) {
        float s = 0.f;
        #pragma unroll
        for (int q = 0; q < 8; q++) s += red[t][q];
        g_pi[i0+t] = 1.f/(1.f + __expf(-(s + bb2[0])));
    }
}

// ---------------- kernel B: K_eps tile (64x64) -> fp16 + partial rowsums ----
__global__ __launch_bounds__(256)
void keps_kernel()
{
    const int i0 = blockIdx.y * 64, j0 = blockIdx.x * 64;
    const int t = threadIdx.x;
    const int tx = t & 15, ty = t >> 4;
    __shared__ float xi[64][16];
    __shared__ float xjT[16][64];
    __shared__ float si[64], sj[64];
    __shared__ float rs[64][17];
    {
        const int r = t >> 2, c = (t & 3) * 4;
        float4 a = *(const float4*)&g_xproj[(i0 + r)*LDIM + c];
        *(float4*)&xi[r][c] = a;
        float4 b = *(const float4*)&g_xproj[(j0 + r)*LDIM + c];
        xjT[c+0][r] = b.x; xjT[c+1][r] = b.y; xjT[c+2][r] = b.z; xjT[c+3][r] = b.w;
    }
    if (t < 64) { si[t] = g_sqn[i0+t]; sj[t] = g_sqn[j0+t]; }
    __syncthreads();

    float bj[4][16];
    float sjr[4];
    #pragma unroll
    for (int n = 0; n < 4; n++) {
        const int jj = tx*4 + n;
        sjr[n] = sj[jj];
        #pragma unroll
        for (int q = 0; q < 16; q++) bj[n][q] = xjT[q][jj];
    }
    #pragma unroll
    for (int m = 0; m < 4; m++) {
        const int ii = ty*4 + m;
        float a[16];
        #pragma unroll
        for (int q = 0; q < 16; q++) a[q] = xi[ii][q];
        const float sii = si[ii];
        float o[4]; float rsum = 0.f;
        #pragma unroll
        for (int n = 0; n < 4; n++) {
            float dot = 0.f;
            #pragma unroll
            for (int q = 0; q < 16; q++) dot += a[q]*bj[n][q];
            float kv = __expf(-CEXP*(sii + sjr[n] - 2.f*dot));
            o[n] = kv; rsum += kv;
        }
        const size_t base = (size_t)(i0+ii)*NTOK + j0 + tx*4;
        *(__half2*)&g_kf16[base]   = __floats2half2_rn(o[0], o[1]);
        *(__half2*)&g_kf16[base+2] = __floats2half2_rn(o[2], o[3]);
        rs[ii][tx] = rsum;
    }
    __syncthreads();
    if (t < 64) {
        float s = 0.f;
        #pragma unroll
        for (int c = 0; c < 16; c++) s += rs[t][c];
        g_qpart[(i0 + t)*32 + blockIdx.x] = s;   // transposed: contiguous per row
    }
}

// ---------------- kernel C: v = pi / q_tilde (contiguous partials) ----------
__global__ void v_kernel()
{
    const int j = blockIdx.x*256 + threadIdx.x;
    if (j < NTOK) {
        const float4* qp = (const float4*)&g_qpart[j*32];
        float q = 0.f;
        #pragma unroll
        for (int p = 0; p < 8; p++) {
            float4 f = qp[p];
            q += f.x + f.y + f.z + f.w;
        }
        g_v[j] = g_pi[j] / q;
    }
}

// ---------------- transpose f_w -> fp16 f_w^T -------------
__global__ __launch_bounds__(256)
void transpose_fw_kernel(const float* __restrict__ in)
{
    __shared__ float tile[32][33];
    const int r0 = blockIdx.y*32, c0 = blockIdx.x*32;
    const int tx = threadIdx.x & 31, ty0 = threadIdx.x >> 5;
    #pragma unroll
    for (int p = 0; p < 4; p++) {
        const int ty = ty0 + p*8;
        tile[ty][tx] = in[(size_t)(r0+ty)*DDIM + c0+tx];
    }
    __syncthreads();
    #pragma unroll
    for (int p = 0; p < 4; p++) {
        const int ty = ty0 + p*8;
        g_fwT16[(size_t)(c0+ty)*DDIM + r0+tx] = __float2half(tile[tx][ty]);
    }
}

// ---------------- transpose + row scale -> fp16 ((v*target)^T) -------------
__global__ __launch_bounds__(256)
void transpose_tvt_kernel()
{
    __shared__ float tile[32][33];
    const int r0 = blockIdx.y*32, c0 = blockIdx.x*32;
    const int tx = threadIdx.x & 31, ty0 = threadIdx.x >> 5;
    #pragma unroll
    for (int p = 0; p < 4; p++) {
        const int ty = ty0 + p*8;
        tile[ty][tx] = g_target[(size_t)(r0+ty)*DDIM + c0+tx] * g_v[r0+ty];
    }
    __syncthreads();
    #pragma unroll
    for (int p = 0; p < 4; p++) {
        const int ty = ty0 + p*8;
        g_tvt16[(size_t)(c0+ty)*NTOK + r0+tx] = __float2half(tile[tx][ty]);
    }
}

// ---------------- unified fp16 pipelined GEMM ------------------------------
// C[2048,768](f32) = A[2048,K] @ B[768,K]^T (+bias).  A,B fp16 K-major.
// BM=128 BN=64 BK=32, 8 warps (4 M x 2 N), warp tile 32x32, double-buffered.
#define GAPAD 40           // padded row elems
#define GROWB 80           // bytes per row
#define GSTG_B0 10240      // A region = 128*80
#define GSTG_BYTES 15360   // + B 64*80
template<bool ADD_BIAS>
__device__ __forceinline__
void gemm16_body(const __half* __restrict__ A, const __half* __restrict__ B,
                 const float* __restrict__ bias, float* __restrict__ C, int K)
{
    __shared__ __align__(16) char smem_raw[2*GSTG_BYTES];   // 30.7 KB
    const uint32_t sbase = smem_u32(smem_raw);
    const int tid = threadIdx.x;
    const int lane = tid & 31, w = tid >> 5;
    const int wm = w >> 1, wn = w & 1;
    const int m0 = blockIdx.y * 128, n0 = blockIdx.x * 64;

    // cp.async: 768 x 16B per chunk, 3 per thread
    uint64_t srcs[3]; uint32_t dsts[3];
    #pragma unroll
    for (int it = 0; it < 3; it++) {
        const int idx = tid + it*256;
        if (idx < 512) {
            const int r = idx >> 2, q = idx & 3;
            srcs[it] = (uint64_t)__cvta_generic_to_global(A + (size_t)(m0+r)*K + q*8);
            dsts[it] = r*GROWB + q*16;
        } else {
            const int j = idx - 512;
            const int r = j >> 2, q = j & 3;
            srcs[it] = (uint64_t)__cvta_generic_to_global(B + (size_t)(n0+r)*K + q*8);
            dsts[it] = GSTG_B0 + r*GROWB + q*16;
        }
    }

    const uint32_t aRow = wm*32 + (lane & 7) + ((lane >> 3) & 1)*8;
    const uint32_t aCol = ((lane >> 4) & 1)*8;
    const uint32_t bRowBase = wn*32 + ((lane >> 4) & 1)*8 + (lane & 7);
    const uint32_t bCol = ((lane >> 3) & 1)*8;
    uint32_t aOff[2], bOff[2];
    #pragma unroll
    for (int mt = 0; mt < 2; mt++) aOff[mt] = (aRow + mt*16)*GROWB + aCol*2;
    #pragma unroll
    for (int np = 0; np < 2; np++) bOff[np] = GSTG_B0 + (bRowBase + np*16)*GROWB + bCol*2;

    float acc[2][2][2][4] = {};   // [mt][np][j][4]

    #pragma unroll
    for (int it = 0; it < 3; it++) cp16(sbase + dsts[it], srcs[it]);
    CP_COMMIT();

    const int nch = K >> 5;
    for (int c = 0; c < nch; c++) {
        const uint32_t so = sbase + (uint32_t)(c & 1)*GSTG_BYTES;
        if (c + 1 < nch) {
            const uint32_t sn = sbase + (uint32_t)((c+1) & 1)*GSTG_BYTES;
            const uint64_t adv = (uint64_t)(c+1)*64;   // 32 elems * 2B
            #pragma unroll
            for (int it = 0; it < 3; it++) cp16(sn + dsts[it], srcs[it] + adv);
            CP_COMMIT();
            CP_WAIT1();
        } else {
            CP_WAIT0();
        }
        __syncthreads();

        #pragma unroll
        for (int kk = 0; kk < 2; kk++) {
            const uint32_t kb = kk * 32;
            uint32_t Af[2][4], Bf[2][4];
            ldsm_x4(Af[0], so + aOff[0] + kb);
            ldsm_x4(Af[1], so + aOff[1] + kb);
            ldsm_x4(Bf[0], so + bOff[0] + kb);
            ldsm_x4(Bf[1], so + bOff[1] + kb);
            #pragma unroll
            for (int mt = 0; mt < 2; mt++)
                #pragma unroll
                for (int np = 0; np < 2; np++) {
                    mma16816h(acc[mt][np][0], Af[mt], &Bf[np][0]);
                    mma16816h(acc[mt][np][1], Af[mt], &Bf[np][2]);
                }
        }
        __syncthreads();
    }

    const int g = lane >> 2, tg2 = (lane & 3)*2;
    #pragma unroll
    for (int mt = 0; mt < 2; mt++) {
        const int row = m0 + wm*32 + mt*16 + g;
        #pragma unroll
        for (int np = 0; np < 2; np++)
            #pragma unroll
            for (int j = 0; j < 2; j++) {
                const int col = n0 + wn*32 + np*16 + j*8 + tg2;
                float b0 = 0.f, b1 = 0.f;
                if (ADD_BIAS) { b0 = bias[col]; b1 = bias[col+1]; }
                const float* cc = acc[mt][np][j];
                *(float2*)&C[(size_t)row*DDIM + col] = make_float2(cc[0]+b0, cc[1]+b1);
                *(float2*)&C[(size_t)(row+8)*DDIM + col] = make_float2(cc[2]+b0, cc[3]+b1);
            }
    }
}

__global__ __launch_bounds__(256)
void gemm_target_kernel(const float* __restrict__ fb)
{
    gemm16_body<true>(g_x16, g_fwT16, fb, g_target, DDIM);
}
__global__ __launch_bounds__(256)
void gemm_S_kernel()
{
    gemm16_body<false>(g_kf16, g_tvt16, nullptr, g_S, NTOK);
}

// ---------------- final: d_i + combine + LayerNorm(768) ----------------
__global__ __launch_bounds__(256)
void final_kernel(const float* __restrict__ x, const float* __restrict__ dtp,
                  const float* __restrict__ g2, const float* __restrict__ b2,
                  float* __restrict__ out)
{
    const int i = blockIdx.x;
    const int t = threadIdx.x;
    __shared__ float rsm[256], rqm[256];
    __shared__ float invd_s, mu_s, is_s;

    // fused dvec: d_i = K_eps[i,:] . v + 1e-5
    {
        const __half2* krow = (const __half2*)&g_kf16[(size_t)i*NTOK];
        const int h = t*4;
        __half2 k0 = krow[h], k1 = krow[h+1], k2 = krow[h+2], k3 = krow[h+3];
        float4 v0 = *(const float4*)&g_v[t*8];
        float4 v1 = *(const float4*)&g_v[t*8+4];
        float2 f0 = __half22float2(k0), f1 = __half22float2(k1);
        float2 f2 = __half22float2(k2), f3 = __half22float2(k3);
        rsm[t] = f0.x*v0.x + f0.y*v0.y + f1.x*v0.z + f1.y*v0.w
               + f2.x*v1.x + f2.y*v1.y + f3.x*v1.z + f3.y*v1.w;
    }
    __syncthreads();
    for (int s = 128; s > 0; s >>= 1) {
        if (t < s) rsm[t] += rsm[t+s];
        __syncthreads();
    }
    if (t == 0) invd_s = (1.f/EPSILON_) / (rsm[0] + 1e-5f);
    __syncthreads();

    const float dtv = dtp[0];
    const float invd = invd_s;

    float vals[3];
    float sum = 0.f, sq = 0.f;
    #pragma unroll
    for (int c = 0; c < 3; c++) {
        const int d = t + c*256;
        const float tg = g_target[(size_t)i*DDIM + d];
        const float tt = dtv * (invd * g_S[(size_t)i*DDIM + d] - tg);
        const float t2 = 0.7f * x[(size_t)i*DDIM + d] + 0.3f*(tg + 2.f*tt);
        vals[c] = t2; sum += t2; sq += t2*t2;
    }
    __syncthreads();
    rsm[t] = sum; rqm[t] = sq;
    __syncthreads();
    for (int s = 128; s > 0; s >>= 1) {
        if (t < s) { rsm[t] += rsm[t+s]; rqm[t] += rqm[t+s]; }
        __syncthreads();
    }
    if (t == 0) {
        float mu = rsm[0] * (1.f/DDIM);
        float var = rqm[0] * (1.f/DDIM) - mu*mu;
        mu_s = mu; is_s = rsqrtf(var + 1e-5f);
    }
    __syncthreads();
    #pragma unroll
    for (int c = 0; c < 3; c++) {
        const int d = t + c*256;
        out[(size_t)i*DDIM + d] = (vals[c]-mu_s)*is_s*g2[d] + b2[d];
    }
}

// ---------------- launch (pure kernel launches; nothing else) ----------------
extern "C" void kernel_launch(void* const* d_in, const int* in_sizes, int n_in,
                              void* d_out, int out_size)
{
    const float* x      = (const float*)d_in[0];
    const float* proj_w = (const float*)d_in[1];
    const float* proj_b = (const float*)d_in[2];
    const float* ln1_g  = (const float*)d_in[3];
    const float* ln1_b  = (const float*)d_in[4];
    const float* pi_w1  = (const float*)d_in[5];
    const float* pi_b1  = (const float*)d_in[6];
    const float* pi_w2  = (const float*)d_in[7];
    const float* pi_b2  = (const float*)d_in[8];
    const float* dt     = (const float*)d_in[9];
    const float* f_w    = (const float*)d_in[10];
    const float* f_b    = (const float*)d_in[11];
    const float* ln2_g  = (const float*)d_in[12];
    const float* ln2_b  = (const float*)d_in[13];
    float* out = (float*)d_out;

    proj_pi_kernel<<<NTOK/4, 256>>>(x, proj_w, proj_b, ln1_g, ln1_b,
                                    pi_w1, pi_b1, pi_w2, pi_b2);
    transpose_fw_kernel<<<dim3(DDIM/32, DDIM/32), 256>>>(f_w);
    keps_kernel<<<dim3(32,32), 256>>>();
    v_kernel<<<8, 256>>>();
    gemm_target_kernel<<<dim3(DDIM/64, NTOK/128), 256>>>(f_b);
    transpose_tvt_kernel<<<dim3(DDIM/32, NTOK/32), 256>>>();
    gemm_S_kernel<<<dim3(DDIM/64, NTOK/128), 256>>>();
    final_kernel<<<NTOK, 256>>>(x, dt, ln2_g, ln2_b, out);
}